// round 1
// baseline (speedup 1.0000x reference)
#include <cuda_runtime.h>
#include <cuda_bf16.h>
#include <math_constants.h>

// Problem constants
#define Bsz 4
#define Ssz 2048
#define Dm  1024
#define Hh  16
#define Dk  64

// ---------------- scratch (device globals; no allocation allowed) ----------
__device__ float g_q[(size_t)Bsz * Hh * Ssz * Dk];   // [B,H,S,Dk]
__device__ float g_k[(size_t)Bsz * Hh * Ssz * Dk];
__device__ float g_v[(size_t)Bsz * Hh * Ssz * Dk];
__device__ float g_x[(size_t)Bsz * Ssz * Dm];        // attention output, [B,S,D]

// ---------------- GEMM: C[M,N] = A[M,K] @ W[N,K]^T + bias[N] ----------------
// 128x128 tile, BK=8, 256 threads, 8x8 microtile per thread.
// MODE 0: plain row-major store C[m*N+n]
// MODE 1: head-split store out[((b*H+h)*S+s)*Dk + dk], b=m/S, s=m%S, h=n>>6, dk=n&63
#define BM 128
#define BN 128
#define BK 8

template <int MODE>
__global__ __launch_bounds__(256)
void gemm_bias_kernel(const float* __restrict__ A, const float* __restrict__ W,
                      const float* __restrict__ bias, float* __restrict__ C,
                      int M, int N, int K)
{
    __shared__ __align__(16) float As[BK][BM + 4];
    __shared__ __align__(16) float Bs[BK][BN + 4];

    const int tid = threadIdx.x;
    const int tx = tid & 15;       // 0..15 -> N microtiles
    const int ty = tid >> 4;       // 0..15 -> M microtiles
    const int m0 = blockIdx.y * BM;
    const int n0 = blockIdx.x * BN;

    float acc[8][8];
#pragma unroll
    for (int i = 0; i < 8; i++)
#pragma unroll
        for (int j = 0; j < 8; j++) acc[i][j] = 0.f;

    const int lrow = tid >> 1;            // 0..127
    const int lcf  = (tid & 1) * 4;       // 0 or 4

    for (int k0 = 0; k0 < K; k0 += BK) {
        // load A tile (128x8) and W tile (128x8), store transposed [k][m]
        float4 av = *(const float4*)&A[(size_t)(m0 + lrow) * K + k0 + lcf];
        float4 wv = *(const float4*)&W[(size_t)(n0 + lrow) * K + k0 + lcf];
        As[lcf + 0][lrow] = av.x; As[lcf + 1][lrow] = av.y;
        As[lcf + 2][lrow] = av.z; As[lcf + 3][lrow] = av.w;
        Bs[lcf + 0][lrow] = wv.x; Bs[lcf + 1][lrow] = wv.y;
        Bs[lcf + 2][lrow] = wv.z; Bs[lcf + 3][lrow] = wv.w;
        __syncthreads();

#pragma unroll
        for (int k = 0; k < BK; k++) {
            float4 a0 = *(const float4*)&As[k][ty * 8];
            float4 a1 = *(const float4*)&As[k][ty * 8 + 4];
            float4 b0 = *(const float4*)&Bs[k][tx * 8];
            float4 b1 = *(const float4*)&Bs[k][tx * 8 + 4];
            float a[8] = {a0.x, a0.y, a0.z, a0.w, a1.x, a1.y, a1.z, a1.w};
            float b[8] = {b0.x, b0.y, b0.z, b0.w, b1.x, b1.y, b1.z, b1.w};
#pragma unroll
            for (int i = 0; i < 8; i++)
#pragma unroll
                for (int j = 0; j < 8; j++)
                    acc[i][j] = fmaf(a[i], b[j], acc[i][j]);
        }
        __syncthreads();
    }

#pragma unroll
    for (int i = 0; i < 8; i++) {
        const int m = m0 + ty * 8 + i;
#pragma unroll
        for (int j = 0; j < 8; j++) {
            const int n = n0 + tx * 8 + j;
            const float val = acc[i][j] + bias[n];
            if (MODE == 0) {
                C[(size_t)m * N + n] = val;
            } else {
                const int bb = m / Ssz, s = m % Ssz;
                const int h = n >> 6, dk = n & 63;
                C[(((size_t)(bb * Hh + h)) * Ssz + s) * Dk + dk] = val;
            }
        }
    }
}

// ---------------- flash attention (fp32, online softmax) -------------------
// grid: (S/64, H, B); block 256 threads.
// Each CTA: 64 query rows for one (b,h). Stream K/V in 64-key tiles.
#define QT 64
#define KT 64
#define SPAD 68   // smem row stride (float), mult of 4 for float4

__global__ __launch_bounds__(256)
void flash_kernel(const float* __restrict__ q, const float* __restrict__ k,
                  const float* __restrict__ v, const int* __restrict__ mask,
                  float* __restrict__ x)
{
    extern __shared__ __align__(16) float sm[];
    float* Qs = sm;                    // [64][68]
    float* Ks = sm + QT * SPAD;        // [64][68]
    float* Vs = sm + 2 * QT * SPAD;    // [64][68]
    float* Sc = sm + 3 * QT * SPAD;    // [64][68]

    const int b  = blockIdx.z;
    const int h  = blockIdx.y;
    const int q0 = blockIdx.x * QT;
    const int tid = threadIdx.x;
    const int tx = tid & 15, ty = tid >> 4;   // score microtile mapping
    const int t  = tid & 3,  r  = tid >> 2;   // softmax mapping: row r, dim-quarter t

    // load Q tile [64][64] -> Qs
    const float* qbase = q + (((size_t)(b * Hh + h)) * Ssz + q0) * Dk;
    for (int i = tid; i < QT * (Dk / 4); i += 256) {
        const int row = i >> 4, cf = (i & 15) * 4;
        *(float4*)&Qs[row * SPAD + cf] = *(const float4*)&qbase[row * Dk + cf];
    }

    float m_old = -CUDART_INF_F;
    float l = 0.f;
    float accv[16];
#pragma unroll
    for (int i = 0; i < 16; i++) accv[i] = 0.f;

    for (int j0 = 0; j0 < Ssz; j0 += KT) {
        __syncthreads();   // protect Ks/Vs (prev softmax read) and Sc
        const float* kbase = k + (((size_t)(b * Hh + h)) * Ssz + j0) * Dk;
        const float* vbase = v + (((size_t)(b * Hh + h)) * Ssz + j0) * Dk;
        for (int i = tid; i < KT * (Dk / 4); i += 256) {
            const int row = i >> 4, cf = (i & 15) * 4;
            *(float4*)&Ks[row * SPAD + cf] = *(const float4*)&kbase[row * Dk + cf];
            *(float4*)&Vs[row * SPAD + cf] = *(const float4*)&vbase[row * Dk + cf];
        }
        __syncthreads();

        // scores: 64x64, 4x4 microtile per thread
        float c[4][4];
#pragma unroll
        for (int i = 0; i < 4; i++)
#pragma unroll
            for (int j = 0; j < 4; j++) c[i][j] = 0.f;

#pragma unroll 8
        for (int d = 0; d < Dk; d++) {
            float a[4], bb4[4];
#pragma unroll
            for (int i = 0; i < 4; i++) a[i]   = Qs[(ty * 4 + i) * SPAD + d];
#pragma unroll
            for (int j = 0; j < 4; j++) bb4[j] = Ks[(tx * 4 + j) * SPAD + d];
#pragma unroll
            for (int i = 0; i < 4; i++)
#pragma unroll
                for (int j = 0; j < 4; j++)
                    c[i][j] = fmaf(a[i], bb4[j], c[i][j]);
        }

        // scale + mask, write to Sc
        const int* mbase = mask + ((size_t)b * Ssz + q0) * Ssz + j0;
#pragma unroll
        for (int i = 0; i < 4; i++) {
            const int qr = ty * 4 + i;
#pragma unroll
            for (int j = 0; j < 4; j++) {
                const int kc = tx * 4 + j;
                const int mm = mbase[(size_t)qr * Ssz + kc];
                Sc[qr * SPAD + kc] = mm ? c[i][j] * 0.125f : -1e9f;
            }
        }
        __syncthreads();

        // online softmax update (each quad of 4 threads handles row r; state
        // m_old/l kept redundantly per thread)
        float tmax = -CUDART_INF_F;
#pragma unroll 8
        for (int cix = 0; cix < KT; cix++) tmax = fmaxf(tmax, Sc[r * SPAD + cix]);
        const float m_new = fmaxf(m_old, tmax);
        const float corr = __expf(m_old - m_new);
        l *= corr;
#pragma unroll
        for (int dd = 0; dd < 16; dd++) accv[dd] *= corr;

#pragma unroll 4
        for (int cix = 0; cix < KT; cix++) {
            const float p = __expf(Sc[r * SPAD + cix] - m_new);
            l += p;
            const float* vrow = &Vs[cix * SPAD + t * 16];
#pragma unroll
            for (int dd = 0; dd < 16; dd++)
                accv[dd] = fmaf(p, vrow[dd], accv[dd]);
        }
        m_old = m_new;
    }

    const float inv = 1.f / l;
    float* xout = x + ((size_t)b * Ssz + (q0 + r)) * Dm + h * Dk + t * 16;
#pragma unroll
    for (int dd = 0; dd < 16; dd++) xout[dd] = accv[dd] * inv;
}

// ---------------- launch ----------------------------------------------------
extern "C" void kernel_launch(void* const* d_in, const int* in_sizes, int n_in,
                              void* d_out, int out_size)
{
    (void)in_sizes; (void)n_in; (void)out_size;
    const float* query  = (const float*)d_in[0];
    const float* key_in = (const float*)d_in[1];
    const float* value  = (const float*)d_in[2];
    const int*   mask   = (const int*)  d_in[3];
    const float* Wq = (const float*)d_in[4];
    const float* bq = (const float*)d_in[5];
    const float* Wk = (const float*)d_in[6];
    const float* bk = (const float*)d_in[7];
    const float* Wv = (const float*)d_in[8];
    const float* bv = (const float*)d_in[9];
    const float* Wo = (const float*)d_in[10];
    const float* bo = (const float*)d_in[11];
    float* out = (float*)d_out;

    float *qp, *kp, *vp, *xp;
    cudaGetSymbolAddress((void**)&qp, g_q);
    cudaGetSymbolAddress((void**)&kp, g_k);
    cudaGetSymbolAddress((void**)&vp, g_v);
    cudaGetSymbolAddress((void**)&xp, g_x);

    const int M = Bsz * Ssz;   // 8192
    const int N = Dm;          // 1024
    const int K = Dm;          // 1024
    dim3 ggrid(N / BN, M / BM);   // (8, 64)

    // projections -> head-split scratch
    gemm_bias_kernel<1><<<ggrid, 256>>>(query,  Wq, bq, qp, M, N, K);
    gemm_bias_kernel<1><<<ggrid, 256>>>(key_in, Wk, bk, kp, M, N, K);
    gemm_bias_kernel<1><<<ggrid, 256>>>(value,  Wv, bv, vp, M, N, K);

    // flash attention
    const int smem = 4 * QT * SPAD * sizeof(float);  // 69632 B
    cudaFuncSetAttribute(flash_kernel, cudaFuncAttributeMaxDynamicSharedMemorySize, smem);
    dim3 fgrid(Ssz / QT, Hh, Bsz);                   // (32, 16, 4)
    flash_kernel<<<fgrid, 256, smem>>>(qp, kp, vp, mask, xp);

    // output projection -> d_out
    gemm_bias_kernel<0><<<ggrid, 256>>>(xp, Wo, bo, out, M, N, K);
}

// round 3
// speedup vs baseline: 5.0181x; 5.0181x over previous
#include <cuda_runtime.h>
#include <cuda_bf16.h>
#include <math_constants.h>
#include <cstdint>

#define Bsz 4
#define Ssz 2048
#define Dm  1024
#define Hh  16
#define Dk  64
#define BH  (Bsz * Hh)

// ---------------- scratch (device globals; no allocation allowed) ----------
__device__ __align__(1024) __nv_bfloat16 g_qh[(size_t)BH * Ssz * Dk];
__device__ __align__(1024) __nv_bfloat16 g_ql[(size_t)BH * Ssz * Dk];
__device__ __align__(1024) __nv_bfloat16 g_kh[(size_t)BH * Ssz * Dk];
__device__ __align__(1024) __nv_bfloat16 g_kl[(size_t)BH * Ssz * Dk];
__device__ __align__(1024) __nv_bfloat16 g_vh[(size_t)BH * Ssz * Dk];
__device__ __align__(1024) __nv_bfloat16 g_vl[(size_t)BH * Ssz * Dk];
__device__ __align__(1024) __nv_bfloat16 g_ah[(size_t)Bsz * Ssz * Dm];
__device__ __align__(1024) __nv_bfloat16 g_al[(size_t)Bsz * Ssz * Dm];
__device__ __align__(1024) __nv_bfloat16 g_wh[(size_t)Dm * Dm];
__device__ __align__(1024) __nv_bfloat16 g_wl[(size_t)Dm * Dm];

// ---------------- PTX helpers ----------------------------------------------
__device__ __forceinline__ uint32_t smem_u32(const void* p) {
    uint32_t a;
    asm("{ .reg .u64 t; cvta.to.shared.u64 t, %1; cvt.u32.u64 %0, t; }" : "=r"(a) : "l"(p));
    return a;
}
__device__ __forceinline__ void cp16(uint32_t dst, const void* src) {
    asm volatile("cp.async.cg.shared.global [%0], [%1], 16;" :: "r"(dst), "l"(src));
}
__device__ __forceinline__ void cp_commit() { asm volatile("cp.async.commit_group;"); }
__device__ __forceinline__ void cp_wait0()  { asm volatile("cp.async.wait_group 0;"); }
__device__ __forceinline__ void cp_wait1()  { asm volatile("cp.async.wait_group 1;"); }

__device__ __forceinline__ void ldsm4(uint32_t* r, uint32_t a) {
    asm volatile("ldmatrix.sync.aligned.m8n8.x4.shared.b16 {%0,%1,%2,%3}, [%4];"
                 : "=r"(r[0]), "=r"(r[1]), "=r"(r[2]), "=r"(r[3]) : "r"(a));
}
__device__ __forceinline__ void ldsm4t(uint32_t* r, uint32_t a) {
    asm volatile("ldmatrix.sync.aligned.m8n8.x4.trans.shared.b16 {%0,%1,%2,%3}, [%4];"
                 : "=r"(r[0]), "=r"(r[1]), "=r"(r[2]), "=r"(r[3]) : "r"(a));
}
__device__ __forceinline__ void mma16816(float* d, const uint32_t* a, const uint32_t* b) {
    asm volatile("mma.sync.aligned.m16n8k16.row.col.f32.bf16.bf16.f32 "
                 "{%0,%1,%2,%3}, {%4,%5,%6,%7}, {%8,%9}, {%0,%1,%2,%3};"
                 : "+f"(d[0]), "+f"(d[1]), "+f"(d[2]), "+f"(d[3])
                 : "r"(a[0]), "r"(a[1]), "r"(a[2]), "r"(a[3]), "r"(b[0]), "r"(b[1]));
}
__device__ __forceinline__ uint32_t pack_bf16(float lo, float hi) {
    uint32_t r;
    asm("cvt.rn.bf16x2.f32 %0, %1, %2;" : "=r"(r) : "f"(hi), "f"(lo));
    return r;
}
// split (v0,v1) into hi bf16x2 + residual-lo bf16x2
__device__ __forceinline__ void split2(float v0, float v1, uint32_t& hp, uint32_t& lp) {
    hp = pack_bf16(v0, v1);
    __nv_bfloat162 h2 = *reinterpret_cast<__nv_bfloat162*>(&hp);
    float r0 = v0 - __bfloat162float(h2.x);
    float r1 = v1 - __bfloat162float(h2.y);
    lp = pack_bf16(r0, r1);
}
__device__ __forceinline__ float qmax(float v) {
    v = fmaxf(v, __shfl_xor_sync(0xffffffffu, v, 1));
    v = fmaxf(v, __shfl_xor_sync(0xffffffffu, v, 2));
    return v;
}
__device__ __forceinline__ float qsum(float v) {
    v += __shfl_xor_sync(0xffffffffu, v, 1);
    v += __shfl_xor_sync(0xffffffffu, v, 2);
    return v;
}

// ---------------- fp32 -> bf16 hi/lo split conversion -----------------------
__global__ __launch_bounds__(256)
void cvt_kernel(const float* __restrict__ src, __nv_bfloat16* __restrict__ hi,
                __nv_bfloat16* __restrict__ lo, int n4)
{
    const int i = blockIdx.x * 256 + threadIdx.x;
    if (i >= n4) return;
    float4 v = ((const float4*)src)[i];
    uint32_t h0, l0, h1, l1;
    split2(v.x, v.y, h0, l0);
    split2(v.z, v.w, h1, l1);
    ((uint2*)hi)[i] = make_uint2(h0, h1);
    ((uint2*)lo)[i] = make_uint2(l0, l1);
}

// ---------------- tensor-core split-bf16 GEMM -------------------------------
// C[M=8192,N=1024] = (Ah+Al)[M,K] @ (Wh+Wl)[N,K]^T + bias (3-pass bf16)
// 128x128 CTA tile, 8 warps (4x2), warp tile 32x64, BK=32, cp.async x2 stages.
#define GSTRIDE 80            // smem row stride bytes (32 bf16 + pad)
#define GARR    10240         // 128 * 80
#define GSTAGE  40960         // 4 arrays (Ah,Al,Wh,Wl)
#define GEMM_SMEM (2 * GSTAGE)

__device__ __forceinline__ void gemm_load(uint32_t sb, int stage, int c, int tid,
                                          int m0, int n0,
                                          const __nv_bfloat16* Ah, const __nv_bfloat16* Al,
                                          const __nv_bfloat16* Wh, const __nv_bfloat16* Wl)
{
#pragma unroll
    for (int it = 0; it < 8; it++) {
        const int flat = it * 256 + tid;
        const int arr = flat >> 9, rem = flat & 511;
        const int row = rem >> 2, seg = rem & 3;
        const __nv_bfloat16* src = (arr == 0) ? Ah : (arr == 1) ? Al : (arr == 2) ? Wh : Wl;
        const int gbase = (arr < 2) ? m0 : n0;
        cp16(sb + stage * GSTAGE + arr * GARR + row * GSTRIDE + seg * 16,
             src + (size_t)(gbase + row) * Dm + c * 32 + seg * 8);
    }
    cp_commit();
}

template <int MODE>   // 0: fp32 row-major C; 1: head-split bf16 hi/lo (Oh,Ol)
__global__ __launch_bounds__(256)
void tgemm(const __nv_bfloat16* __restrict__ Ah, const __nv_bfloat16* __restrict__ Al,
           const __nv_bfloat16* __restrict__ Wh, const __nv_bfloat16* __restrict__ Wl,
           const float* __restrict__ bias, float* __restrict__ C,
           __nv_bfloat16* __restrict__ Oh, __nv_bfloat16* __restrict__ Ol)
{
    extern __shared__ char smem[];
    const uint32_t sb = smem_u32(smem);
    const int tid = threadIdx.x;
    const int lane = tid & 31, w = tid >> 5;
    const int wm = w >> 1, wn = w & 1;
    const int m0 = blockIdx.y * 128, n0 = blockIdx.x * 128;

    float acc[2][8][4];
#pragma unroll
    for (int mt = 0; mt < 2; mt++)
#pragma unroll
        for (int nt = 0; nt < 8; nt++)
#pragma unroll
            for (int r = 0; r < 4; r++) acc[mt][nt][r] = 0.f;

    gemm_load(sb, 0, 0, tid, m0, n0, Ah, Al, Wh, Wl);

    for (int c = 0; c < 32; c++) {
        if (c + 1 < 32) { gemm_load(sb, (c + 1) & 1, c + 1, tid, m0, n0, Ah, Al, Wh, Wl); cp_wait1(); }
        else cp_wait0();
        __syncthreads();
        const uint32_t st = sb + (c & 1) * GSTAGE;
#pragma unroll
        for (int kt = 0; kt < 2; kt++) {
            uint32_t a_h[2][4], a_l[2][4];
#pragma unroll
            for (int mt = 0; mt < 2; mt++) {
                const uint32_t ra = st +
                    (uint32_t)(wm * 32 + mt * 16 + ((lane >> 3) & 1) * 8 + (lane & 7)) * GSTRIDE +
                    kt * 32 + (lane >> 4) * 16;
                ldsm4(a_h[mt], ra);
                ldsm4(a_l[mt], ra + GARR);
            }
#pragma unroll
            for (int nt2 = 0; nt2 < 4; nt2++) {
                const uint32_t rb = st + 2 * GARR +
                    (uint32_t)(wn * 64 + nt2 * 16 + (lane >> 4) * 8 + (lane & 7)) * GSTRIDE +
                    kt * 32 + ((lane >> 3) & 1) * 16;
                uint32_t b_h[4], b_l[4];
                ldsm4(b_h, rb);
                ldsm4(b_l, rb + GARR);
#pragma unroll
                for (int mt = 0; mt < 2; mt++) {
                    mma16816(acc[mt][nt2 * 2],     a_h[mt], b_h);
                    mma16816(acc[mt][nt2 * 2 + 1], a_h[mt], b_h + 2);
                    mma16816(acc[mt][nt2 * 2],     a_h[mt], b_l);
                    mma16816(acc[mt][nt2 * 2 + 1], a_h[mt], b_l + 2);
                    mma16816(acc[mt][nt2 * 2],     a_l[mt], b_h);
                    mma16816(acc[mt][nt2 * 2 + 1], a_l[mt], b_h + 2);
                }
            }
        }
        __syncthreads();
    }

    // epilogue
    const int grp = lane >> 2, qc = lane & 3;
#pragma unroll
    for (int mt = 0; mt < 2; mt++) {
#pragma unroll
        for (int nt = 0; nt < 8; nt++) {
            const int row = m0 + wm * 32 + mt * 16 + grp;
            const int col = n0 + wn * 64 + nt * 8 + qc * 2;
            const float b0 = bias[col], b1 = bias[col + 1];
            const float v0 = acc[mt][nt][0] + b0, v1 = acc[mt][nt][1] + b1;
            const float v2 = acc[mt][nt][2] + b0, v3 = acc[mt][nt][3] + b1;
            if (MODE == 0) {
                *(float2*)&C[(size_t)row * Dm + col]       = make_float2(v0, v1);
                *(float2*)&C[(size_t)(row + 8) * Dm + col] = make_float2(v2, v3);
            } else {
                const int hh = col >> 6, dk = col & 63;
                {
                    const int bb = row >> 11, s = row & 2047;
                    const size_t idx = (((size_t)(bb * Hh + hh)) * Ssz + s) * Dk + dk;
                    uint32_t hp, lp; split2(v0, v1, hp, lp);
                    *(uint32_t*)&Oh[idx] = hp; *(uint32_t*)&Ol[idx] = lp;
                }
                {
                    const int r2 = row + 8;
                    const int bb = r2 >> 11, s = r2 & 2047;
                    const size_t idx = (((size_t)(bb * Hh + hh)) * Ssz + s) * Dk + dk;
                    uint32_t hp, lp; split2(v2, v3, hp, lp);
                    *(uint32_t*)&Oh[idx] = hp; *(uint32_t*)&Ol[idx] = lp;
                }
            }
        }
    }
}

// ---------------- tensorized flash attention --------------------------------
// CTA: 128 q-rows of one (b,h); 8 warps, warp owns 16 rows. K/V tiles of 64.
#define FQ 128
#define FK 64
#define FSTR 144                 // smem row stride bytes (64 bf16 + pad)
#define QH_OFF 0
#define QL_OFF 18432
#define KV_OFF 36864
#define KVST   36864             // per stage: Kh,Kl,Vh,Vl each 9216
#define KL_O 9216
#define VH_O 18432
#define VL_O 27648
#define PH_OFF 110592
#define PL_OFF 129024
#define FLASH_SMEM 147456

__device__ __forceinline__ void flash_load_kv(uint32_t sb, int j, int tid, size_t bh,
                                              const __nv_bfloat16* kh, const __nv_bfloat16* kl,
                                              const __nv_bfloat16* vh, const __nv_bfloat16* vl)
{
#pragma unroll
    for (int it = 0; it < 8; it++) {
        const int flat = it * 256 + tid;
        const int arr = flat >> 9, rem = flat & 511;
        const int row = rem >> 3, seg = rem & 7;
        const __nv_bfloat16* src = (arr == 0) ? kh : (arr == 1) ? kl : (arr == 2) ? vh : vl;
        cp16(sb + KV_OFF + (j & 1) * KVST + arr * 9216 + row * FSTR + seg * 16,
             src + ((size_t)bh * Ssz + j * FK + row) * Dk + seg * 8);
    }
    cp_commit();
}

__global__ __launch_bounds__(256, 1)
void flash(const __nv_bfloat16* __restrict__ qh, const __nv_bfloat16* __restrict__ ql,
           const __nv_bfloat16* __restrict__ kh, const __nv_bfloat16* __restrict__ kl,
           const __nv_bfloat16* __restrict__ vh, const __nv_bfloat16* __restrict__ vl,
           const int* __restrict__ mask,
           __nv_bfloat16* __restrict__ xh, __nv_bfloat16* __restrict__ xl)
{
    extern __shared__ char smem[];
    const uint32_t sb = smem_u32(smem);
    const int tid = threadIdx.x, lane = tid & 31, w = tid >> 5;
    const int b = blockIdx.z, h = blockIdx.y, q0 = blockIdx.x * FQ;
    const size_t bh = (size_t)(b * Hh + h);
    const int grp = lane >> 2, qc = lane & 3;

    // preload KV stage 0, then Q
    flash_load_kv(sb, 0, tid, bh, kh, kl, vh, vl);
#pragma unroll
    for (int it = 0; it < 8; it++) {
        const int flat = it * 256 + tid;
        const int arr = flat >> 10, rem = flat & 1023;
        const int row = rem >> 3, seg = rem & 7;
        const __nv_bfloat16* src = (arr == 0) ? qh : ql;
        cp16(sb + arr * QL_OFF + row * FSTR + seg * 16,
             src + ((size_t)bh * Ssz + q0 + row) * Dk + seg * 8);
    }
    cp_commit();

    float acc_o[8][4];
#pragma unroll
    for (int nt = 0; nt < 8; nt++)
#pragma unroll
        for (int r = 0; r < 4; r++) acc_o[nt][r] = 0.f;
    float m_a = -CUDART_INF_F, m_b = -CUDART_INF_F, l_a = 0.f, l_b = 0.f;

    const int NJT = Ssz / FK;   // 32
    for (int jt = 0; jt < NJT; jt++) {
        const int j0 = jt * FK;
        // mask prefetch (gmem, independent of smem)
        int2 mk[2][8];
        const int* mra = mask + ((size_t)b * Ssz + (q0 + w * 16 + grp)) * Ssz + j0;
#pragma unroll
        for (int nt = 0; nt < 8; nt++) {
            mk[0][nt] = *(const int2*)(mra + nt * 8 + qc * 2);
            mk[1][nt] = *(const int2*)(mra + 8 * Ssz + nt * 8 + qc * 2);
        }
        if (jt + 1 < NJT) { flash_load_kv(sb, jt + 1, tid, bh, kh, kl, vh, vl); cp_wait1(); }
        else cp_wait0();
        __syncthreads();
        const uint32_t st = sb + KV_OFF + (jt & 1) * KVST;

        // ---- QK^T: s[16 rows][64 keys] per warp, 3-pass bf16 ----
        float s[8][4];
#pragma unroll
        for (int nt = 0; nt < 8; nt++)
#pragma unroll
            for (int r = 0; r < 4; r++) s[nt][r] = 0.f;
#pragma unroll
        for (int kt = 0; kt < 4; kt++) {
            const uint32_t aq = sb + QH_OFF +
                (uint32_t)(w * 16 + ((lane >> 3) & 1) * 8 + (lane & 7)) * FSTR +
                kt * 32 + (lane >> 4) * 16;
            uint32_t a_h[4], a_l[4];
            ldsm4(a_h, aq);
            ldsm4(a_l, aq + QL_OFF);
#pragma unroll
            for (int nt2 = 0; nt2 < 4; nt2++) {
                const uint32_t rb = st +
                    (uint32_t)(nt2 * 16 + (lane >> 4) * 8 + (lane & 7)) * FSTR +
                    kt * 32 + ((lane >> 3) & 1) * 16;
                uint32_t b_h[4], b_l[4];
                ldsm4(b_h, rb);
                ldsm4(b_l, rb + KL_O);
                mma16816(s[nt2 * 2],     a_h, b_h);
                mma16816(s[nt2 * 2 + 1], a_h, b_h + 2);
                mma16816(s[nt2 * 2],     a_h, b_l);
                mma16816(s[nt2 * 2 + 1], a_h, b_l + 2);
                mma16816(s[nt2 * 2],     a_l, b_h);
                mma16816(s[nt2 * 2 + 1], a_l, b_h + 2);
            }
        }

        // ---- scale + mask + online softmax ----
        float ra = -CUDART_INF_F, rb = -CUDART_INF_F;
#pragma unroll
        for (int nt = 0; nt < 8; nt++) {
            s[nt][0] = mk[0][nt].x ? s[nt][0] * 0.125f : -1e9f;
            s[nt][1] = mk[0][nt].y ? s[nt][1] * 0.125f : -1e9f;
            s[nt][2] = mk[1][nt].x ? s[nt][2] * 0.125f : -1e9f;
            s[nt][3] = mk[1][nt].y ? s[nt][3] * 0.125f : -1e9f;
            ra = fmaxf(ra, fmaxf(s[nt][0], s[nt][1]));
            rb = fmaxf(rb, fmaxf(s[nt][2], s[nt][3]));
        }
        ra = qmax(ra); rb = qmax(rb);
        const float mna = fmaxf(m_a, ra), mnb = fmaxf(m_b, rb);
        const float ca = __expf(m_a - mna), cb = __expf(m_b - mnb);
        float suma = 0.f, sumb = 0.f;
        const uint32_t prow_a = sb + (uint32_t)(w * 16 + grp) * FSTR + qc * 4;
        const uint32_t prow_b = prow_a + 8 * FSTR;
#pragma unroll
        for (int nt = 0; nt < 8; nt++) {
            const float p0 = __expf(s[nt][0] - mna), p1 = __expf(s[nt][1] - mna);
            const float p2 = __expf(s[nt][2] - mnb), p3 = __expf(s[nt][3] - mnb);
            suma += p0 + p1; sumb += p2 + p3;
            uint32_t hp, lp;
            split2(p0, p1, hp, lp);
            *(uint32_t*)(smem + PH_OFF + (prow_a - sb) + nt * 16) = hp;
            *(uint32_t*)(smem + PL_OFF + (prow_a - sb) + nt * 16) = lp;
            split2(p2, p3, hp, lp);
            *(uint32_t*)(smem + PH_OFF + (prow_b - sb) + nt * 16) = hp;
            *(uint32_t*)(smem + PL_OFF + (prow_b - sb) + nt * 16) = lp;
        }
        l_a = l_a * ca + qsum(suma);
        l_b = l_b * cb + qsum(sumb);
#pragma unroll
        for (int nt = 0; nt < 8; nt++) {
            acc_o[nt][0] *= ca; acc_o[nt][1] *= ca;
            acc_o[nt][2] *= cb; acc_o[nt][3] *= cb;
        }
        m_a = mna; m_b = mnb;
        __syncwarp();

        // ---- P @ V, 3-pass ----
#pragma unroll
        for (int kt2 = 0; kt2 < 4; kt2++) {
            const uint32_t ap = sb + PH_OFF +
                (uint32_t)(w * 16 + ((lane >> 3) & 1) * 8 + (lane & 7)) * FSTR +
                kt2 * 32 + (lane >> 4) * 16;
            uint32_t p_h[4], p_l[4];
            ldsm4(p_h, ap);
            ldsm4(p_l, ap + (PL_OFF - PH_OFF));
#pragma unroll
            for (int nd2 = 0; nd2 < 4; nd2++) {
                const uint32_t vb = st + VH_O +
                    (uint32_t)(kt2 * 16 + ((lane >> 3) & 1) * 8 + (lane & 7)) * FSTR +
                    nd2 * 32 + (lane >> 4) * 16;
                uint32_t v_h[4], v_l[4];
                ldsm4t(v_h, vb);
                ldsm4t(v_l, vb + (VL_O - VH_O));
                mma16816(acc_o[nd2 * 2],     p_h, v_h);
                mma16816(acc_o[nd2 * 2 + 1], p_h, v_h + 2);
                mma16816(acc_o[nd2 * 2],     p_h, v_l);
                mma16816(acc_o[nd2 * 2 + 1], p_h, v_l + 2);
                mma16816(acc_o[nd2 * 2],     p_l, v_h);
                mma16816(acc_o[nd2 * 2 + 1], p_l, v_h + 2);
            }
        }
        __syncthreads();
    }

    // epilogue: x[b][s][h*64+d] as bf16 hi/lo
    const float inva = 1.f / l_a, invb = 1.f / l_b;
    const int row_a = q0 + w * 16 + grp;
#pragma unroll
    for (int nt = 0; nt < 8; nt++) {
        const int col = h * Dk + nt * 8 + qc * 2;
        uint32_t hp, lp;
        split2(acc_o[nt][0] * inva, acc_o[nt][1] * inva, hp, lp);
        size_t idx = ((size_t)b * Ssz + row_a) * Dm + col;
        *(uint32_t*)&xh[idx] = hp; *(uint32_t*)&xl[idx] = lp;
        split2(acc_o[nt][2] * invb, acc_o[nt][3] * invb, hp, lp);
        idx = ((size_t)b * Ssz + row_a + 8) * Dm + col;
        *(uint32_t*)&xh[idx] = hp; *(uint32_t*)&xl[idx] = lp;
    }
}

// ---------------- launch ----------------------------------------------------
extern "C" void kernel_launch(void* const* d_in, const int* in_sizes, int n_in,
                              void* d_out, int out_size)
{
    (void)in_sizes; (void)n_in; (void)out_size;
    const float* query  = (const float*)d_in[0];
    const float* key_in = (const float*)d_in[1];
    const float* value  = (const float*)d_in[2];
    const int*   mask   = (const int*)  d_in[3];
    const float* Wq = (const float*)d_in[4];
    const float* bq = (const float*)d_in[5];
    const float* Wk = (const float*)d_in[6];
    const float* bk = (const float*)d_in[7];
    const float* Wv = (const float*)d_in[8];
    const float* bv = (const float*)d_in[9];
    const float* Wo = (const float*)d_in[10];
    const float* bo = (const float*)d_in[11];
    float* out = (float*)d_out;

    __nv_bfloat16 *qhp, *qlp, *khp, *klp, *vhp, *vlp, *ah, *al, *wh, *wl;
    cudaGetSymbolAddress((void**)&qhp, g_qh);
    cudaGetSymbolAddress((void**)&qlp, g_ql);
    cudaGetSymbolAddress((void**)&khp, g_kh);
    cudaGetSymbolAddress((void**)&klp, g_kl);
    cudaGetSymbolAddress((void**)&vhp, g_vh);
    cudaGetSymbolAddress((void**)&vlp, g_vl);
    cudaGetSymbolAddress((void**)&ah, g_ah);
    cudaGetSymbolAddress((void**)&al, g_al);
    cudaGetSymbolAddress((void**)&wh, g_wh);
    cudaGetSymbolAddress((void**)&wl, g_wl);

    cudaFuncSetAttribute(tgemm<0>, cudaFuncAttributeMaxDynamicSharedMemorySize, GEMM_SMEM);
    cudaFuncSetAttribute(tgemm<1>, cudaFuncAttributeMaxDynamicSharedMemorySize, GEMM_SMEM);
    cudaFuncSetAttribute(flash, cudaFuncAttributeMaxDynamicSharedMemorySize, FLASH_SMEM);

    const int M = Bsz * Ssz;                  // 8192
    dim3 ggrid(Dm / 128, M / 128);            // (8, 64)
    const int NA4 = (M * Dm) / 4;             // 2097152
    const int NW4 = (Dm * Dm) / 4;            // 262144

    // Q projection
    cvt_kernel<<<NW4 / 256, 256>>>(Wq, wh, wl, NW4);
    cvt_kernel<<<NA4 / 256, 256>>>(query, ah, al, NA4);
    tgemm<1><<<ggrid, 256, GEMM_SMEM>>>(ah, al, wh, wl, bq, nullptr, qhp, qlp);
    // K projection
    cvt_kernel<<<NW4 / 256, 256>>>(Wk, wh, wl, NW4);
    cvt_kernel<<<NA4 / 256, 256>>>(key_in, ah, al, NA4);
    tgemm<1><<<ggrid, 256, GEMM_SMEM>>>(ah, al, wh, wl, bk, nullptr, khp, klp);
    // V projection
    cvt_kernel<<<NW4 / 256, 256>>>(Wv, wh, wl, NW4);
    cvt_kernel<<<NA4 / 256, 256>>>(value, ah, al, NA4);
    tgemm<1><<<ggrid, 256, GEMM_SMEM>>>(ah, al, wh, wl, bv, nullptr, vhp, vlp);

    // attention (writes x hi/lo directly into g_ah/g_al)
    dim3 fgrid(Ssz / FQ, Hh, Bsz);            // (16, 16, 4)
    flash<<<fgrid, 256, FLASH_SMEM>>>(qhp, qlp, khp, klp, vhp, vlp, mask, ah, al);

    // output projection
    cvt_kernel<<<NW4 / 256, 256>>>(Wo, wh, wl, NW4);
    tgemm<0><<<ggrid, 256, GEMM_SMEM>>>(ah, al, wh, wl, bo, out, nullptr, nullptr);
}

// round 4
// speedup vs baseline: 6.1952x; 1.2346x over previous
#include <cuda_runtime.h>
#include <cuda_bf16.h>
#include <math_constants.h>
#include <cstdint>

#define Bsz 4
#define Ssz 2048
#define Dm  1024
#define Hh  16
#define Dk  64
#define BH  (Bsz * Hh)

// ---------------- scratch (device globals; no allocation allowed) ----------
__device__ __align__(1024) __nv_bfloat16 g_qh[(size_t)BH * Ssz * Dk];
__device__ __align__(1024) __nv_bfloat16 g_ql[(size_t)BH * Ssz * Dk];
__device__ __align__(1024) __nv_bfloat16 g_kh[(size_t)BH * Ssz * Dk];
__device__ __align__(1024) __nv_bfloat16 g_kl[(size_t)BH * Ssz * Dk];
__device__ __align__(1024) __nv_bfloat16 g_vh[(size_t)BH * Ssz * Dk];
__device__ __align__(1024) __nv_bfloat16 g_vl[(size_t)BH * Ssz * Dk];
__device__ __align__(1024) __nv_bfloat16 g_ah[(size_t)Bsz * Ssz * Dm];
__device__ __align__(1024) __nv_bfloat16 g_al[(size_t)Bsz * Ssz * Dm];
__device__ __align__(1024) __nv_bfloat16 g_wh[(size_t)Dm * Dm];
__device__ __align__(1024) __nv_bfloat16 g_wl[(size_t)Dm * Dm];
__device__ __align__(1024) uint32_t g_mb[(size_t)Bsz * Ssz * (Ssz / 32)];

// ---------------- PTX helpers ----------------------------------------------
__device__ __forceinline__ uint32_t smem_u32(const void* p) {
    uint32_t a;
    asm("{ .reg .u64 t; cvta.to.shared.u64 t, %1; cvt.u32.u64 %0, t; }" : "=r"(a) : "l"(p));
    return a;
}
__device__ __forceinline__ void cp16(uint32_t dst, const void* src) {
    asm volatile("cp.async.cg.shared.global [%0], [%1], 16;" :: "r"(dst), "l"(src));
}
__device__ __forceinline__ void cp_commit() { asm volatile("cp.async.commit_group;"); }
__device__ __forceinline__ void cp_wait0()  { asm volatile("cp.async.wait_group 0;"); }
__device__ __forceinline__ void cp_wait1()  { asm volatile("cp.async.wait_group 1;"); }

__device__ __forceinline__ void ldsm4(uint32_t* r, uint32_t a) {
    asm volatile("ldmatrix.sync.aligned.m8n8.x4.shared.b16 {%0,%1,%2,%3}, [%4];"
                 : "=r"(r[0]), "=r"(r[1]), "=r"(r[2]), "=r"(r[3]) : "r"(a));
}
__device__ __forceinline__ void ldsm4t(uint32_t* r, uint32_t a) {
    asm volatile("ldmatrix.sync.aligned.m8n8.x4.trans.shared.b16 {%0,%1,%2,%3}, [%4];"
                 : "=r"(r[0]), "=r"(r[1]), "=r"(r[2]), "=r"(r[3]) : "r"(a));
}
__device__ __forceinline__ void mma16816(float* d, const uint32_t* a, const uint32_t* b) {
    asm volatile("mma.sync.aligned.m16n8k16.row.col.f32.bf16.bf16.f32 "
                 "{%0,%1,%2,%3}, {%4,%5,%6,%7}, {%8,%9}, {%0,%1,%2,%3};"
                 : "+f"(d[0]), "+f"(d[1]), "+f"(d[2]), "+f"(d[3])
                 : "r"(a[0]), "r"(a[1]), "r"(a[2]), "r"(a[3]), "r"(b[0]), "r"(b[1]));
}
__device__ __forceinline__ uint32_t pack_bf16(float lo, float hi) {
    uint32_t r;
    asm("cvt.rn.bf16x2.f32 %0, %1, %2;" : "=r"(r) : "f"(hi), "f"(lo));
    return r;
}
__device__ __forceinline__ void split2(float v0, float v1, uint32_t& hp, uint32_t& lp) {
    hp = pack_bf16(v0, v1);
    __nv_bfloat162 h2 = *reinterpret_cast<__nv_bfloat162*>(&hp);
    float r0 = v0 - __bfloat162float(h2.x);
    float r1 = v1 - __bfloat162float(h2.y);
    lp = pack_bf16(r0, r1);
}
__device__ __forceinline__ float qmax(float v) {
    v = fmaxf(v, __shfl_xor_sync(0xffffffffu, v, 1));
    v = fmaxf(v, __shfl_xor_sync(0xffffffffu, v, 2));
    return v;
}
__device__ __forceinline__ float qsum(float v) {
    v += __shfl_xor_sync(0xffffffffu, v, 1);
    v += __shfl_xor_sync(0xffffffffu, v, 2);
    return v;
}

// ---------------- fp32 -> bf16 hi/lo split conversion -----------------------
__global__ __launch_bounds__(256)
void cvt_kernel(const float* __restrict__ src, __nv_bfloat16* __restrict__ hi,
                __nv_bfloat16* __restrict__ lo, int n4)
{
    const int i = blockIdx.x * 256 + threadIdx.x;
    if (i >= n4) return;
    float4 v = ((const float4*)src)[i];
    uint32_t h0, l0, h1, l1;
    split2(v.x, v.y, h0, l0);
    split2(v.z, v.w, h1, l1);
    ((uint2*)hi)[i] = make_uint2(h0, h1);
    ((uint2*)lo)[i] = make_uint2(l0, l1);
}

// ---------------- mask -> bitmask pack --------------------------------------
__global__ __launch_bounds__(256)
void maskpack_kernel(const int* __restrict__ mask, uint32_t* __restrict__ bits)
{
    const int i = blockIdx.x * 256 + threadIdx.x;
    const uint32_t b = __ballot_sync(0xffffffffu, mask[i] != 0);
    if ((threadIdx.x & 31) == 0) bits[i >> 5] = b;
}

// ---------------- tensor-core split-bf16 GEMM -------------------------------
#define GSTRIDE 80
#define GARR    10240
#define GSTAGE  40960
#define GEMM_SMEM (2 * GSTAGE)

__device__ __forceinline__ void gemm_load(uint32_t sb, int stage, int c, int tid,
                                          int m0, int n0,
                                          const __nv_bfloat16* Ah, const __nv_bfloat16* Al,
                                          const __nv_bfloat16* Wh, const __nv_bfloat16* Wl)
{
#pragma unroll
    for (int it = 0; it < 8; it++) {
        const int flat = it * 256 + tid;
        const int arr = flat >> 9, rem = flat & 511;
        const int row = rem >> 2, seg = rem & 3;
        const __nv_bfloat16* src = (arr == 0) ? Ah : (arr == 1) ? Al : (arr == 2) ? Wh : Wl;
        const int gbase = (arr < 2) ? m0 : n0;
        cp16(sb + stage * GSTAGE + arr * GARR + row * GSTRIDE + seg * 16,
             src + (size_t)(gbase + row) * Dm + c * 32 + seg * 8);
    }
    cp_commit();
}

template <int MODE>   // 0: fp32 row-major C; 1: head-split bf16 hi/lo (Oh,Ol)
__global__ __launch_bounds__(256, 2)
void tgemm(const __nv_bfloat16* __restrict__ Ah, const __nv_bfloat16* __restrict__ Al,
           const __nv_bfloat16* __restrict__ Wh, const __nv_bfloat16* __restrict__ Wl,
           const float* __restrict__ bias, float* __restrict__ C,
           __nv_bfloat16* __restrict__ Oh, __nv_bfloat16* __restrict__ Ol)
{
    extern __shared__ char smem[];
    const uint32_t sb = smem_u32(smem);
    const int tid = threadIdx.x;
    const int lane = tid & 31, w = tid >> 5;
    const int wm = w >> 1, wn = w & 1;
    const int m0 = blockIdx.y * 128, n0 = blockIdx.x * 128;

    float acc[2][8][4];
#pragma unroll
    for (int mt = 0; mt < 2; mt++)
#pragma unroll
        for (int nt = 0; nt < 8; nt++)
#pragma unroll
            for (int r = 0; r < 4; r++) acc[mt][nt][r] = 0.f;

    gemm_load(sb, 0, 0, tid, m0, n0, Ah, Al, Wh, Wl);

    for (int c = 0; c < 32; c++) {
        if (c + 1 < 32) { gemm_load(sb, (c + 1) & 1, c + 1, tid, m0, n0, Ah, Al, Wh, Wl); cp_wait1(); }
        else cp_wait0();
        __syncthreads();
        const uint32_t st = sb + (c & 1) * GSTAGE;
#pragma unroll
        for (int kt = 0; kt < 2; kt++) {
            uint32_t a_h[2][4], a_l[2][4];
#pragma unroll
            for (int mt = 0; mt < 2; mt++) {
                const uint32_t ra = st +
                    (uint32_t)(wm * 32 + mt * 16 + ((lane >> 3) & 1) * 8 + (lane & 7)) * GSTRIDE +
                    kt * 32 + (lane >> 4) * 16;
                ldsm4(a_h[mt], ra);
                ldsm4(a_l[mt], ra + GARR);
            }
#pragma unroll
            for (int nt2 = 0; nt2 < 4; nt2++) {
                const uint32_t rb = st + 2 * GARR +
                    (uint32_t)(wn * 64 + nt2 * 16 + (lane >> 4) * 8 + (lane & 7)) * GSTRIDE +
                    kt * 32 + ((lane >> 3) & 1) * 16;
                uint32_t b_h[4], b_l[4];
                ldsm4(b_h, rb);
                ldsm4(b_l, rb + GARR);
#pragma unroll
                for (int mt = 0; mt < 2; mt++) {
                    mma16816(acc[mt][nt2 * 2],     a_h[mt], b_h);
                    mma16816(acc[mt][nt2 * 2 + 1], a_h[mt], b_h + 2);
                    mma16816(acc[mt][nt2 * 2],     a_h[mt], b_l);
                    mma16816(acc[mt][nt2 * 2 + 1], a_h[mt], b_l + 2);
                    mma16816(acc[mt][nt2 * 2],     a_l[mt], b_h);
                    mma16816(acc[mt][nt2 * 2 + 1], a_l[mt], b_h + 2);
                }
            }
        }
        __syncthreads();
    }

    const int grp = lane >> 2, qc = lane & 3;
#pragma unroll
    for (int mt = 0; mt < 2; mt++) {
#pragma unroll
        for (int nt = 0; nt < 8; nt++) {
            const int row = m0 + wm * 32 + mt * 16 + grp;
            const int col = n0 + wn * 64 + nt * 8 + qc * 2;
            const float b0 = bias[col], b1 = bias[col + 1];
            const float v0 = acc[mt][nt][0] + b0, v1 = acc[mt][nt][1] + b1;
            const float v2 = acc[mt][nt][2] + b0, v3 = acc[mt][nt][3] + b1;
            if (MODE == 0) {
                *(float2*)&C[(size_t)row * Dm + col]       = make_float2(v0, v1);
                *(float2*)&C[(size_t)(row + 8) * Dm + col] = make_float2(v2, v3);
            } else {
                const int hh = col >> 6, dk = col & 63;
                {
                    const int bb = row >> 11, s = row & 2047;
                    const size_t idx = (((size_t)(bb * Hh + hh)) * Ssz + s) * Dk + dk;
                    uint32_t hp, lp; split2(v0, v1, hp, lp);
                    *(uint32_t*)&Oh[idx] = hp; *(uint32_t*)&Ol[idx] = lp;
                }
                {
                    const int r2 = row + 8;
                    const int bb = r2 >> 11, s = r2 & 2047;
                    const size_t idx = (((size_t)(bb * Hh + hh)) * Ssz + s) * Dk + dk;
                    uint32_t hp, lp; split2(v2, v3, hp, lp);
                    *(uint32_t*)&Oh[idx] = hp; *(uint32_t*)&Ol[idx] = lp;
                }
            }
        }
    }
}

// ---------------- tensorized flash attention (P in registers) ---------------
#define FQ 128
#define FK 64
#define FSTR 144
#define QH_OFF 0
#define QL_OFF 18432
#define KV_OFF 36864
#define KVST   36864
#define KL_O 9216
#define VH_O 18432
#define VL_O 27648
#define FLASH_SMEM 110592   // 108 KB -> 2 CTAs/SM

__device__ __forceinline__ void flash_load_kv(uint32_t sb, int j, int tid, size_t bh,
                                              const __nv_bfloat16* kh, const __nv_bfloat16* kl,
                                              const __nv_bfloat16* vh, const __nv_bfloat16* vl)
{
#pragma unroll
    for (int it = 0; it < 8; it++) {
        const int flat = it * 256 + tid;
        const int arr = flat >> 9, rem = flat & 511;
        const int row = rem >> 3, seg = rem & 7;
        const __nv_bfloat16* src = (arr == 0) ? kh : (arr == 1) ? kl : (arr == 2) ? vh : vl;
        cp16(sb + KV_OFF + (j & 1) * KVST + arr * 9216 + row * FSTR + seg * 16,
             src + ((size_t)bh * Ssz + j * FK + row) * Dk + seg * 8);
    }
    cp_commit();
}

__global__ __launch_bounds__(256, 2)
void flash(const __nv_bfloat16* __restrict__ qh, const __nv_bfloat16* __restrict__ ql,
           const __nv_bfloat16* __restrict__ kh, const __nv_bfloat16* __restrict__ kl,
           const __nv_bfloat16* __restrict__ vh, const __nv_bfloat16* __restrict__ vl,
           const uint32_t* __restrict__ mb,
           __nv_bfloat16* __restrict__ xh, __nv_bfloat16* __restrict__ xl)
{
    extern __shared__ char smem[];
    const uint32_t sb = smem_u32(smem);
    const int tid = threadIdx.x, lane = tid & 31, w = tid >> 5;
    const int b = blockIdx.z, h = blockIdx.y, q0 = blockIdx.x * FQ;
    const size_t bh = (size_t)(b * Hh + h);
    const int grp = lane >> 2, qc = lane & 3;
    const int row_a = q0 + w * 16 + grp;

    flash_load_kv(sb, 0, tid, bh, kh, kl, vh, vl);
#pragma unroll
    for (int it = 0; it < 8; it++) {
        const int flat = it * 256 + tid;
        const int arr = flat >> 10, rem = flat & 1023;
        const int row = rem >> 3, seg = rem & 7;
        const __nv_bfloat16* src = (arr == 0) ? qh : ql;
        cp16(sb + arr * QL_OFF + row * FSTR + seg * 16,
             src + ((size_t)bh * Ssz + q0 + row) * Dk + seg * 8);
    }
    cp_commit();

    float acc_o[8][4];
#pragma unroll
    for (int nt = 0; nt < 8; nt++)
#pragma unroll
        for (int r = 0; r < 4; r++) acc_o[nt][r] = 0.f;
    float m_a = -CUDART_INF_F, m_b = -CUDART_INF_F, l_a = 0.f, l_b = 0.f;

    const uint32_t* mrow_a = mb + ((size_t)b * Ssz + row_a) * (Ssz / 32);
    const uint32_t* mrow_b = mrow_a + 8 * (Ssz / 32);

    const int NJT = Ssz / FK;   // 32
    for (int jt = 0; jt < NJT; jt++) {
        // mask bits for this 64-key tile (2 words per row)
        const uint2 wa = *(const uint2*)(mrow_a + jt * 2);
        const uint2 wb = *(const uint2*)(mrow_b + jt * 2);
        if (jt + 1 < NJT) { flash_load_kv(sb, jt + 1, tid, bh, kh, kl, vh, vl); cp_wait1(); }
        else cp_wait0();
        __syncthreads();
        const uint32_t st = sb + KV_OFF + (jt & 1) * KVST;

        // ---- QK^T ----
        float s[8][4];
#pragma unroll
        for (int nt = 0; nt < 8; nt++)
#pragma unroll
            for (int r = 0; r < 4; r++) s[nt][r] = 0.f;
#pragma unroll
        for (int kt = 0; kt < 4; kt++) {
            const uint32_t aq = sb + QH_OFF +
                (uint32_t)(w * 16 + ((lane >> 3) & 1) * 8 + (lane & 7)) * FSTR +
                kt * 32 + (lane >> 4) * 16;
            uint32_t a_h[4], a_l[4];
            ldsm4(a_h, aq);
            ldsm4(a_l, aq + QL_OFF);
#pragma unroll
            for (int nt2 = 0; nt2 < 4; nt2++) {
                const uint32_t rb = st +
                    (uint32_t)(nt2 * 16 + (lane >> 4) * 8 + (lane & 7)) * FSTR +
                    kt * 32 + ((lane >> 3) & 1) * 16;
                uint32_t b_h[4], b_l[4];
                ldsm4(b_h, rb);
                ldsm4(b_l, rb + KL_O);
                mma16816(s[nt2 * 2],     a_h, b_h);
                mma16816(s[nt2 * 2 + 1], a_h, b_h + 2);
                mma16816(s[nt2 * 2],     a_h, b_l);
                mma16816(s[nt2 * 2 + 1], a_h, b_l + 2);
                mma16816(s[nt2 * 2],     a_l, b_h);
                mma16816(s[nt2 * 2 + 1], a_l, b_h + 2);
            }
        }

        // ---- scale + mask + online softmax (p stays in s[][]) ----
        float ra = -CUDART_INF_F, rbx = -CUDART_INF_F;
#pragma unroll
        for (int nt = 0; nt < 8; nt++) {
            const int kk = nt * 8 + qc * 2;
            const uint32_t wA = (nt < 4) ? wa.x : wa.y;
            const uint32_t wB = (nt < 4) ? wb.x : wb.y;
            const int bit = kk & 31;
            s[nt][0] = ((wA >> bit) & 1)       ? s[nt][0] * 0.125f : -1e9f;
            s[nt][1] = ((wA >> (bit + 1)) & 1) ? s[nt][1] * 0.125f : -1e9f;
            s[nt][2] = ((wB >> bit) & 1)       ? s[nt][2] * 0.125f : -1e9f;
            s[nt][3] = ((wB >> (bit + 1)) & 1) ? s[nt][3] * 0.125f : -1e9f;
            ra  = fmaxf(ra,  fmaxf(s[nt][0], s[nt][1]));
            rbx = fmaxf(rbx, fmaxf(s[nt][2], s[nt][3]));
        }
        ra = qmax(ra); rbx = qmax(rbx);
        const float mna = fmaxf(m_a, ra), mnb = fmaxf(m_b, rbx);
        const float ca = __expf(m_a - mna), cb = __expf(m_b - mnb);
        float suma = 0.f, sumb = 0.f;
#pragma unroll
        for (int nt = 0; nt < 8; nt++) {
            s[nt][0] = __expf(s[nt][0] - mna);
            s[nt][1] = __expf(s[nt][1] - mna);
            s[nt][2] = __expf(s[nt][2] - mnb);
            s[nt][3] = __expf(s[nt][3] - mnb);
            suma += s[nt][0] + s[nt][1];
            sumb += s[nt][2] + s[nt][3];
        }
        l_a = l_a * ca + qsum(suma);
        l_b = l_b * cb + qsum(sumb);
#pragma unroll
        for (int nt = 0; nt < 8; nt++) {
            acc_o[nt][0] *= ca; acc_o[nt][1] *= ca;
            acc_o[nt][2] *= cb; acc_o[nt][3] *= cb;
        }
        m_a = mna; m_b = mnb;

        // ---- P @ V with P fragments built in registers ----
#pragma unroll
        for (int kt2 = 0; kt2 < 4; kt2++) {
            uint32_t p_h[4], p_l[4];
            split2(s[2 * kt2][0],     s[2 * kt2][1],     p_h[0], p_l[0]);
            split2(s[2 * kt2][2],     s[2 * kt2][3],     p_h[1], p_l[1]);
            split2(s[2 * kt2 + 1][0], s[2 * kt2 + 1][1], p_h[2], p_l[2]);
            split2(s[2 * kt2 + 1][2], s[2 * kt2 + 1][3], p_h[3], p_l[3]);
#pragma unroll
            for (int nd2 = 0; nd2 < 4; nd2++) {
                const uint32_t vb = st + VH_O +
                    (uint32_t)(kt2 * 16 + ((lane >> 3) & 1) * 8 + (lane & 7)) * FSTR +
                    nd2 * 32 + (lane >> 4) * 16;
                uint32_t v_h[4], v_l[4];
                ldsm4t(v_h, vb);
                ldsm4t(v_l, vb + (VL_O - VH_O));
                mma16816(acc_o[nd2 * 2],     p_h, v_h);
                mma16816(acc_o[nd2 * 2 + 1], p_h, v_h + 2);
                mma16816(acc_o[nd2 * 2],     p_h, v_l);
                mma16816(acc_o[nd2 * 2 + 1], p_h, v_l + 2);
                mma16816(acc_o[nd2 * 2],     p_l, v_h);
                mma16816(acc_o[nd2 * 2 + 1], p_l, v_h + 2);
            }
        }
        __syncthreads();
    }

    // epilogue
    const float inva = 1.f / l_a, invb = 1.f / l_b;
#pragma unroll
    for (int nt = 0; nt < 8; nt++) {
        const int col = h * Dk + nt * 8 + qc * 2;
        uint32_t hp, lp;
        split2(acc_o[nt][0] * inva, acc_o[nt][1] * inva, hp, lp);
        size_t idx = ((size_t)b * Ssz + row_a) * Dm + col;
        *(uint32_t*)&xh[idx] = hp; *(uint32_t*)&xl[idx] = lp;
        split2(acc_o[nt][2] * invb, acc_o[nt][3] * invb, hp, lp);
        idx = ((size_t)b * Ssz + row_a + 8) * Dm + col;
        *(uint32_t*)&xh[idx] = hp; *(uint32_t*)&xl[idx] = lp;
    }
}

// ---------------- launch ----------------------------------------------------
extern "C" void kernel_launch(void* const* d_in, const int* in_sizes, int n_in,
                              void* d_out, int out_size)
{
    (void)in_sizes; (void)n_in; (void)out_size;
    const float* query  = (const float*)d_in[0];
    const float* key_in = (const float*)d_in[1];
    const float* value  = (const float*)d_in[2];
    const int*   mask   = (const int*)  d_in[3];
    const float* Wq = (const float*)d_in[4];
    const float* bq = (const float*)d_in[5];
    const float* Wk = (const float*)d_in[6];
    const float* bk = (const float*)d_in[7];
    const float* Wv = (const float*)d_in[8];
    const float* bv = (const float*)d_in[9];
    const float* Wo = (const float*)d_in[10];
    const float* bo = (const float*)d_in[11];
    float* out = (float*)d_out;

    __nv_bfloat16 *qhp, *qlp, *khp, *klp, *vhp, *vlp, *ah, *al, *wh, *wl;
    uint32_t* mbp;
    cudaGetSymbolAddress((void**)&qhp, g_qh);
    cudaGetSymbolAddress((void**)&qlp, g_ql);
    cudaGetSymbolAddress((void**)&khp, g_kh);
    cudaGetSymbolAddress((void**)&klp, g_kl);
    cudaGetSymbolAddress((void**)&vhp, g_vh);
    cudaGetSymbolAddress((void**)&vlp, g_vl);
    cudaGetSymbolAddress((void**)&ah, g_ah);
    cudaGetSymbolAddress((void**)&al, g_al);
    cudaGetSymbolAddress((void**)&wh, g_wh);
    cudaGetSymbolAddress((void**)&wl, g_wl);
    cudaGetSymbolAddress((void**)&mbp, g_mb);

    cudaFuncSetAttribute(tgemm<0>, cudaFuncAttributeMaxDynamicSharedMemorySize, GEMM_SMEM);
    cudaFuncSetAttribute(tgemm<1>, cudaFuncAttributeMaxDynamicSharedMemorySize, GEMM_SMEM);
    cudaFuncSetAttribute(flash, cudaFuncAttributeMaxDynamicSharedMemorySize, FLASH_SMEM);

    const int M = Bsz * Ssz;                  // 8192
    dim3 ggrid(Dm / 128, M / 128);            // (8, 64)
    const int NA4 = (M * Dm) / 4;
    const int NW4 = (Dm * Dm) / 4;

    // mask pack (independent of projections)
    maskpack_kernel<<<(Bsz * Ssz * Ssz) / 256, 256>>>(mask, mbp);

    // Q projection
    cvt_kernel<<<NW4 / 256, 256>>>(Wq, wh, wl, NW4);
    cvt_kernel<<<NA4 / 256, 256>>>(query, ah, al, NA4);
    tgemm<1><<<ggrid, 256, GEMM_SMEM>>>(ah, al, wh, wl, bq, nullptr, qhp, qlp);
    // K projection
    cvt_kernel<<<NW4 / 256, 256>>>(Wk, wh, wl, NW4);
    cvt_kernel<<<NA4 / 256, 256>>>(key_in, ah, al, NA4);
    tgemm<1><<<ggrid, 256, GEMM_SMEM>>>(ah, al, wh, wl, bk, nullptr, khp, klp);
    // V projection
    cvt_kernel<<<NW4 / 256, 256>>>(Wv, wh, wl, NW4);
    cvt_kernel<<<NA4 / 256, 256>>>(value, ah, al, NA4);
    tgemm<1><<<ggrid, 256, GEMM_SMEM>>>(ah, al, wh, wl, bv, nullptr, vhp, vlp);

    // attention (writes x hi/lo directly into g_ah/g_al)
    dim3 fgrid(Ssz / FQ, Hh, Bsz);            // (16, 16, 4)
    flash<<<fgrid, 256, FLASH_SMEM>>>(qhp, qlp, khp, klp, vhp, vlp, mbp, ah, al);

    // output projection
    cvt_kernel<<<NW4 / 256, 256>>>(Wo, wh, wl, NW4);
    tgemm<0><<<ggrid, 256, GEMM_SMEM>>>(ah, al, wh, wl, bo, out, nullptr, nullptr);
}

// round 5
// speedup vs baseline: 6.3450x; 1.0242x over previous
#include <cuda_runtime.h>
#include <cuda_bf16.h>
#include <math_constants.h>
#include <cstdint>

#define Bsz 4
#define Ssz 2048
#define Dm  1024
#define Hh  16
#define Dk  64
#define BH  (Bsz * Hh)
#define MD  ((size_t)8192 * 1024)
#define DD  ((size_t)1024 * 1024)

// ---------------- scratch (device globals; no allocation allowed) ----------
__device__ __align__(1024) __nv_bfloat16 g_qh[MD];
__device__ __align__(1024) __nv_bfloat16 g_ql[MD];
__device__ __align__(1024) __nv_bfloat16 g_kh[MD];
__device__ __align__(1024) __nv_bfloat16 g_kl[MD];
__device__ __align__(1024) __nv_bfloat16 g_vh[MD];
__device__ __align__(1024) __nv_bfloat16 g_vl[MD];
__device__ __align__(1024) __nv_bfloat16 g_ah[3 * MD];   // activations hi (q,k,v); slot0 reused for x
__device__ __align__(1024) __nv_bfloat16 g_al[3 * MD];
__device__ __align__(1024) __nv_bfloat16 g_wh[4 * DD];   // weights hi (Wq,Wk,Wv,Wo)
__device__ __align__(1024) __nv_bfloat16 g_wl[4 * DD];
__device__ __align__(1024) uint32_t g_mb[(size_t)Bsz * Ssz * (Ssz / 32)];

// ---------------- PTX helpers ----------------------------------------------
__device__ __forceinline__ uint32_t smem_u32(const void* p) {
    uint32_t a;
    asm("{ .reg .u64 t; cvta.to.shared.u64 t, %1; cvt.u32.u64 %0, t; }" : "=r"(a) : "l"(p));
    return a;
}
__device__ __forceinline__ void cp16(uint32_t dst, const void* src) {
    asm volatile("cp.async.cg.shared.global [%0], [%1], 16;" :: "r"(dst), "l"(src));
}
__device__ __forceinline__ void cp_commit() { asm volatile("cp.async.commit_group;"); }
__device__ __forceinline__ void cp_wait0()  { asm volatile("cp.async.wait_group 0;"); }

__device__ __forceinline__ void ldsm4(uint32_t* r, uint32_t a) {
    asm volatile("ldmatrix.sync.aligned.m8n8.x4.shared.b16 {%0,%1,%2,%3}, [%4];"
                 : "=r"(r[0]), "=r"(r[1]), "=r"(r[2]), "=r"(r[3]) : "r"(a));
}
__device__ __forceinline__ void ldsm4t(uint32_t* r, uint32_t a) {
    asm volatile("ldmatrix.sync.aligned.m8n8.x4.trans.shared.b16 {%0,%1,%2,%3}, [%4];"
                 : "=r"(r[0]), "=r"(r[1]), "=r"(r[2]), "=r"(r[3]) : "r"(a));
}
__device__ __forceinline__ void mma16816(float* d, const uint32_t* a, const uint32_t* b) {
    asm volatile("mma.sync.aligned.m16n8k16.row.col.f32.bf16.bf16.f32 "
                 "{%0,%1,%2,%3}, {%4,%5,%6,%7}, {%8,%9}, {%0,%1,%2,%3};"
                 : "+f"(d[0]), "+f"(d[1]), "+f"(d[2]), "+f"(d[3])
                 : "r"(a[0]), "r"(a[1]), "r"(a[2]), "r"(a[3]), "r"(b[0]), "r"(b[1]));
}
__device__ __forceinline__ uint32_t pack_bf16(float lo, float hi) {
    uint32_t r;
    asm("cvt.rn.bf16x2.f32 %0, %1, %2;" : "=r"(r) : "f"(hi), "f"(lo));
    return r;
}
__device__ __forceinline__ void split2(float v0, float v1, uint32_t& hp, uint32_t& lp) {
    hp = pack_bf16(v0, v1);
    __nv_bfloat162 h2 = *reinterpret_cast<__nv_bfloat162*>(&hp);
    float r0 = v0 - __bfloat162float(h2.x);
    float r1 = v1 - __bfloat162float(h2.y);
    lp = pack_bf16(r0, r1);
}
__device__ __forceinline__ float qmax(float v) {
    v = fmaxf(v, __shfl_xor_sync(0xffffffffu, v, 1));
    v = fmaxf(v, __shfl_xor_sync(0xffffffffu, v, 2));
    return v;
}
__device__ __forceinline__ float qsum(float v) {
    v += __shfl_xor_sync(0xffffffffu, v, 1);
    v += __shfl_xor_sync(0xffffffffu, v, 2);
    return v;
}

// ---------------- fused fp32 -> bf16 hi/lo conversions ----------------------
__global__ __launch_bounds__(256)
void cvtW_kernel(const float* __restrict__ w0, const float* __restrict__ w1,
                 const float* __restrict__ w2, const float* __restrict__ w3)
{
    const int z = blockIdx.z;
    const float* src = (z == 0) ? w0 : (z == 1) ? w1 : (z == 2) ? w2 : w3;
    __nv_bfloat16* hi = g_wh + (size_t)z * DD;
    __nv_bfloat16* lo = g_wl + (size_t)z * DD;
    const int i = blockIdx.x * 256 + threadIdx.x;
    float4 v = ((const float4*)src)[i];
    uint32_t h0, l0, h1, l1;
    split2(v.x, v.y, h0, l0);
    split2(v.z, v.w, h1, l1);
    ((uint2*)hi)[i] = make_uint2(h0, h1);
    ((uint2*)lo)[i] = make_uint2(l0, l1);
}

__global__ __launch_bounds__(256)
void cvtA_kernel(const float* __restrict__ a0, const float* __restrict__ a1,
                 const float* __restrict__ a2)
{
    const int z = blockIdx.z;
    const float* src = (z == 0) ? a0 : (z == 1) ? a1 : a2;
    __nv_bfloat16* hi = g_ah + (size_t)z * MD;
    __nv_bfloat16* lo = g_al + (size_t)z * MD;
    const int i = blockIdx.x * 256 + threadIdx.x;
    float4 v = ((const float4*)src)[i];
    uint32_t h0, l0, h1, l1;
    split2(v.x, v.y, h0, l0);
    split2(v.z, v.w, h1, l1);
    ((uint2*)hi)[i] = make_uint2(h0, h1);
    ((uint2*)lo)[i] = make_uint2(l0, l1);
}

// ---------------- mask -> bitmask pack --------------------------------------
__global__ __launch_bounds__(256)
void maskpack_kernel(const int* __restrict__ mask, uint32_t* __restrict__ bits)
{
    const int i = blockIdx.x * 256 + threadIdx.x;
    const uint32_t b = __ballot_sync(0xffffffffu, mask[i] != 0);
    if ((threadIdx.x & 31) == 0) bits[i >> 5] = b;
}

// ---------------- tensor-core split-bf16 GEMM -------------------------------
#define GSTRIDE 80
#define GARR    10240
#define GSTAGE  40960
#define GEMM_SMEM (2 * GSTAGE)

__device__ __forceinline__ void gemm_load(uint32_t sb, int stage, int c, int tid,
                                          int m0, int n0,
                                          const __nv_bfloat16* Ah, const __nv_bfloat16* Al,
                                          const __nv_bfloat16* Wh, const __nv_bfloat16* Wl)
{
#pragma unroll
    for (int it = 0; it < 8; it++) {
        const int flat = it * 256 + tid;
        const int arr = flat >> 9, rem = flat & 511;
        const int row = rem >> 2, seg = rem & 3;
        const __nv_bfloat16* src = (arr == 0) ? Ah : (arr == 1) ? Al : (arr == 2) ? Wh : Wl;
        const int gbase = (arr < 2) ? m0 : n0;
        cp16(sb + stage * GSTAGE + arr * GARR + row * GSTRIDE + seg * 16,
             src + (size_t)(gbase + row) * Dm + c * 32 + seg * 8);
    }
    cp_commit();
}

// MODE 0: output projection -> fp32 C.  MODE 1: per-z projection -> head-split bf16 hi/lo.
template <int MODE>
__global__ __launch_bounds__(256, 2)
void tgemm(const float* __restrict__ b0p, const float* __restrict__ b1p,
           const float* __restrict__ b2p, float* __restrict__ C)
{
    extern __shared__ char smem[];
    const uint32_t sb = smem_u32(smem);
    const int tid = threadIdx.x;
    const int lane = tid & 31, w = tid >> 5;
    const int wm = w >> 1, wn = w & 1;
    const int m0 = blockIdx.y * 128, n0 = blockIdx.x * 128;
    const int z = (MODE == 1) ? blockIdx.z : 3;

    const __nv_bfloat16* Ah = g_ah + ((MODE == 1) ? (size_t)z * MD : 0);
    const __nv_bfloat16* Al = g_al + ((MODE == 1) ? (size_t)z * MD : 0);
    const __nv_bfloat16* Wh = g_wh + (size_t)z * DD;
    const __nv_bfloat16* Wl = g_wl + (size_t)z * DD;
    const float* bias = (MODE == 0) ? b0p : (z == 0) ? b0p : (z == 1) ? b1p : b2p;
    __nv_bfloat16* Oh = (MODE == 1) ? ((z == 0) ? g_qh : (z == 1) ? g_kh : g_vh) : nullptr;
    __nv_bfloat16* Ol = (MODE == 1) ? ((z == 0) ? g_ql : (z == 1) ? g_kl : g_vl) : nullptr;

    float acc[2][8][4];
#pragma unroll
    for (int mt = 0; mt < 2; mt++)
#pragma unroll
        for (int nt = 0; nt < 8; nt++)
#pragma unroll
            for (int r = 0; r < 4; r++) acc[mt][nt][r] = 0.f;

    gemm_load(sb, 0, 0, tid, m0, n0, Ah, Al, Wh, Wl);

    for (int c = 0; c < 32; c++) {
        cp_wait0();
        __syncthreads();
        if (c + 1 < 32) gemm_load(sb, (c + 1) & 1, c + 1, tid, m0, n0, Ah, Al, Wh, Wl);
        const uint32_t st = sb + (c & 1) * GSTAGE;
#pragma unroll
        for (int kt = 0; kt < 2; kt++) {
            uint32_t a_h[2][4], a_l[2][4];
#pragma unroll
            for (int mt = 0; mt < 2; mt++) {
                const uint32_t ra = st +
                    (uint32_t)(wm * 32 + mt * 16 + ((lane >> 3) & 1) * 8 + (lane & 7)) * GSTRIDE +
                    kt * 32 + (lane >> 4) * 16;
                ldsm4(a_h[mt], ra);
                ldsm4(a_l[mt], ra + GARR);
            }
#pragma unroll
            for (int nt2 = 0; nt2 < 4; nt2++) {
                const uint32_t rb = st + 2 * GARR +
                    (uint32_t)(wn * 64 + nt2 * 16 + (lane >> 4) * 8 + (lane & 7)) * GSTRIDE +
                    kt * 32 + ((lane >> 3) & 1) * 16;
                uint32_t b_h[4], b_l[4];
                ldsm4(b_h, rb);
                ldsm4(b_l, rb + GARR);
#pragma unroll
                for (int mt = 0; mt < 2; mt++) {
                    mma16816(acc[mt][nt2 * 2],     a_h[mt], b_h);
                    mma16816(acc[mt][nt2 * 2 + 1], a_h[mt], b_h + 2);
                    mma16816(acc[mt][nt2 * 2],     a_h[mt], b_l);
                    mma16816(acc[mt][nt2 * 2 + 1], a_h[mt], b_l + 2);
                    mma16816(acc[mt][nt2 * 2],     a_l[mt], b_h);
                    mma16816(acc[mt][nt2 * 2 + 1], a_l[mt], b_h + 2);
                }
            }
        }
    }

    const int grp = lane >> 2, qc = lane & 3;
#pragma unroll
    for (int mt = 0; mt < 2; mt++) {
#pragma unroll
        for (int nt = 0; nt < 8; nt++) {
            const int row = m0 + wm * 32 + mt * 16 + grp;
            const int col = n0 + wn * 64 + nt * 8 + qc * 2;
            const float b0 = bias[col], b1 = bias[col + 1];
            const float v0 = acc[mt][nt][0] + b0, v1 = acc[mt][nt][1] + b1;
            const float v2 = acc[mt][nt][2] + b0, v3 = acc[mt][nt][3] + b1;
            if (MODE == 0) {
                *(float2*)&C[(size_t)row * Dm + col]       = make_float2(v0, v1);
                *(float2*)&C[(size_t)(row + 8) * Dm + col] = make_float2(v2, v3);
            } else {
                const int hh = col >> 6, dk = col & 63;
                {
                    const int bb = row >> 11, s = row & 2047;
                    const size_t idx = (((size_t)(bb * Hh + hh)) * Ssz + s) * Dk + dk;
                    uint32_t hp, lp; split2(v0, v1, hp, lp);
                    *(uint32_t*)&Oh[idx] = hp; *(uint32_t*)&Ol[idx] = lp;
                }
                {
                    const int r2 = row + 8;
                    const int bb = r2 >> 11, s = r2 & 2047;
                    const size_t idx = (((size_t)(bb * Hh + hh)) * Ssz + s) * Dk + dk;
                    uint32_t hp, lp; split2(v2, v3, hp, lp);
                    *(uint32_t*)&Oh[idx] = hp; *(uint32_t*)&Ol[idx] = lp;
                }
            }
        }
    }
}

// ---------------- tensorized flash attention (P in regs, Q-hi hoisted) ------
#define FQ 128
#define FK 64
#define FSTR 144
#define QH_OFF 0
#define QL_OFF 18432
#define KV_OFF 36864
#define KVST   36864
#define KL_O 9216
#define VH_O 18432
#define VL_O 27648
#define FLASH_SMEM 110592   // 108 KB -> 2 CTAs/SM

__device__ __forceinline__ void flash_load_kv(uint32_t sb, int j, int tid, size_t bh)
{
#pragma unroll
    for (int it = 0; it < 8; it++) {
        const int flat = it * 256 + tid;
        const int arr = flat >> 9, rem = flat & 511;
        const int row = rem >> 3, seg = rem & 7;
        const __nv_bfloat16* src = (arr == 0) ? g_kh : (arr == 1) ? g_kl : (arr == 2) ? g_vh : g_vl;
        cp16(sb + KV_OFF + (j & 1) * KVST + arr * 9216 + row * FSTR + seg * 16,
             src + (bh * Ssz + j * FK + row) * Dk + seg * 8);
    }
    cp_commit();
}

__global__ __launch_bounds__(256, 2)
void flash(const uint32_t* __restrict__ mb,
           __nv_bfloat16* __restrict__ xh, __nv_bfloat16* __restrict__ xl)
{
    extern __shared__ char smem[];
    const uint32_t sb = smem_u32(smem);
    const int tid = threadIdx.x, lane = tid & 31, w = tid >> 5;
    const int b = blockIdx.z, h = blockIdx.y, q0 = blockIdx.x * FQ;
    const size_t bh = (size_t)(b * Hh + h);
    const int grp = lane >> 2, qc = lane & 3;
    const int row_a = q0 + w * 16 + grp;

    flash_load_kv(sb, 0, tid, bh);
#pragma unroll
    for (int it = 0; it < 8; it++) {
        const int flat = it * 256 + tid;
        const int arr = flat >> 10, rem = flat & 1023;
        const int row = rem >> 3, seg = rem & 7;
        const __nv_bfloat16* src = (arr == 0) ? g_qh : g_ql;
        cp16(sb + arr * QL_OFF + row * FSTR + seg * 16,
             src + (bh * Ssz + q0 + row) * Dk + seg * 8);
    }
    cp_commit();
    cp_wait0();
    __syncthreads();

    // hoist loop-invariant Q-hi fragments
    const uint32_t qrow = (uint32_t)(w * 16 + ((lane >> 3) & 1) * 8 + (lane & 7)) * FSTR +
                          (lane >> 4) * 16;
    uint32_t qfh[4][4];
#pragma unroll
    for (int kt = 0; kt < 4; kt++) ldsm4(qfh[kt], sb + QH_OFF + qrow + kt * 32);

    float acc_o[8][4];
#pragma unroll
    for (int nt = 0; nt < 8; nt++)
#pragma unroll
        for (int r = 0; r < 4; r++) acc_o[nt][r] = 0.f;
    float m_a = -CUDART_INF_F, m_b = -CUDART_INF_F, l_a = 0.f, l_b = 0.f;

    const uint32_t* mrow_a = mb + ((size_t)b * Ssz + row_a) * (Ssz / 32);
    const uint32_t* mrow_b = mrow_a + 8 * (Ssz / 32);

    const int NJT = Ssz / FK;   // 32
    for (int jt = 0; jt < NJT; jt++) {
        const uint2 wa = *(const uint2*)(mrow_a + jt * 2);
        const uint2 wb = *(const uint2*)(mrow_b + jt * 2);
        if (jt > 0) { cp_wait0(); __syncthreads(); }
        if (jt + 1 < NJT) flash_load_kv(sb, jt + 1, tid, bh);
        const uint32_t st = sb + KV_OFF + (jt & 1) * KVST;

        // ---- QK^T (3-pass) ----
        float s[8][4];
#pragma unroll
        for (int nt = 0; nt < 8; nt++)
#pragma unroll
            for (int r = 0; r < 4; r++) s[nt][r] = 0.f;
#pragma unroll
        for (int kt = 0; kt < 4; kt++) {
            uint32_t a_l[4];
            ldsm4(a_l, sb + QL_OFF + qrow + kt * 32);
#pragma unroll
            for (int nt2 = 0; nt2 < 4; nt2++) {
                const uint32_t rb = st +
                    (uint32_t)(nt2 * 16 + (lane >> 4) * 8 + (lane & 7)) * FSTR +
                    kt * 32 + ((lane >> 3) & 1) * 16;
                uint32_t b_h[4], b_l[4];
                ldsm4(b_h, rb);
                ldsm4(b_l, rb + KL_O);
                mma16816(s[nt2 * 2],     qfh[kt], b_h);
                mma16816(s[nt2 * 2 + 1], qfh[kt], b_h + 2);
                mma16816(s[nt2 * 2],     qfh[kt], b_l);
                mma16816(s[nt2 * 2 + 1], qfh[kt], b_l + 2);
                mma16816(s[nt2 * 2],     a_l, b_h);
                mma16816(s[nt2 * 2 + 1], a_l, b_h + 2);
            }
        }

        // ---- scale + mask + online softmax ----
        float ra = -CUDART_INF_F, rbx = -CUDART_INF_F;
#pragma unroll
        for (int nt = 0; nt < 8; nt++) {
            const int kk = nt * 8 + qc * 2;
            const uint32_t wA = (nt < 4) ? wa.x : wa.y;
            const uint32_t wB = (nt < 4) ? wb.x : wb.y;
            const int bit = kk & 31;
            s[nt][0] = ((wA >> bit) & 1)       ? s[nt][0] * 0.125f : -1e9f;
            s[nt][1] = ((wA >> (bit + 1)) & 1) ? s[nt][1] * 0.125f : -1e9f;
            s[nt][2] = ((wB >> bit) & 1)       ? s[nt][2] * 0.125f : -1e9f;
            s[nt][3] = ((wB >> (bit + 1)) & 1) ? s[nt][3] * 0.125f : -1e9f;
            ra  = fmaxf(ra,  fmaxf(s[nt][0], s[nt][1]));
            rbx = fmaxf(rbx, fmaxf(s[nt][2], s[nt][3]));
        }
        ra = qmax(ra); rbx = qmax(rbx);
        const float mna = fmaxf(m_a, ra), mnb = fmaxf(m_b, rbx);
        const float ca = __expf(m_a - mna), cb = __expf(m_b - mnb);
        float suma = 0.f, sumb = 0.f;
#pragma unroll
        for (int nt = 0; nt < 8; nt++) {
            s[nt][0] = __expf(s[nt][0] - mna);
            s[nt][1] = __expf(s[nt][1] - mna);
            s[nt][2] = __expf(s[nt][2] - mnb);
            s[nt][3] = __expf(s[nt][3] - mnb);
            suma += s[nt][0] + s[nt][1];
            sumb += s[nt][2] + s[nt][3];
        }
        l_a = l_a * ca + qsum(suma);
        l_b = l_b * cb + qsum(sumb);
#pragma unroll
        for (int nt = 0; nt < 8; nt++) {
            acc_o[nt][0] *= ca; acc_o[nt][1] *= ca;
            acc_o[nt][2] *= cb; acc_o[nt][3] *= cb;
        }
        m_a = mna; m_b = mnb;

        // ---- P @ V with P fragments built in registers ----
#pragma unroll
        for (int kt2 = 0; kt2 < 4; kt2++) {
            uint32_t p_h[4], p_l[4];
            split2(s[2 * kt2][0],     s[2 * kt2][1],     p_h[0], p_l[0]);
            split2(s[2 * kt2][2],     s[2 * kt2][3],     p_h[1], p_l[1]);
            split2(s[2 * kt2 + 1][0], s[2 * kt2 + 1][1], p_h[2], p_l[2]);
            split2(s[2 * kt2 + 1][2], s[2 * kt2 + 1][3], p_h[3], p_l[3]);
#pragma unroll
            for (int nd2 = 0; nd2 < 4; nd2++) {
                const uint32_t vb = st + VH_O +
                    (uint32_t)(kt2 * 16 + ((lane >> 3) & 1) * 8 + (lane & 7)) * FSTR +
                    nd2 * 32 + (lane >> 4) * 16;
                uint32_t v_h[4], v_l[4];
                ldsm4t(v_h, vb);
                ldsm4t(v_l, vb + (VL_O - VH_O));
                mma16816(acc_o[nd2 * 2],     p_h, v_h);
                mma16816(acc_o[nd2 * 2 + 1], p_h, v_h + 2);
                mma16816(acc_o[nd2 * 2],     p_h, v_l);
                mma16816(acc_o[nd2 * 2 + 1], p_h, v_l + 2);
                mma16816(acc_o[nd2 * 2],     p_l, v_h);
                mma16816(acc_o[nd2 * 2 + 1], p_l, v_h + 2);
            }
        }
    }

    // epilogue
    const float inva = 1.f / l_a, invb = 1.f / l_b;
#pragma unroll
    for (int nt = 0; nt < 8; nt++) {
        const int col = h * Dk + nt * 8 + qc * 2;
        uint32_t hp, lp;
        split2(acc_o[nt][0] * inva, acc_o[nt][1] * inva, hp, lp);
        size_t idx = ((size_t)b * Ssz + row_a) * Dm + col;
        *(uint32_t*)&xh[idx] = hp; *(uint32_t*)&xl[idx] = lp;
        split2(acc_o[nt][2] * invb, acc_o[nt][3] * invb, hp, lp);
        idx = ((size_t)b * Ssz + row_a + 8) * Dm + col;
        *(uint32_t*)&xh[idx] = hp; *(uint32_t*)&xl[idx] = lp;
    }
}

// ---------------- launch ----------------------------------------------------
extern "C" void kernel_launch(void* const* d_in, const int* in_sizes, int n_in,
                              void* d_out, int out_size)
{
    (void)in_sizes; (void)n_in; (void)out_size;
    const float* query  = (const float*)d_in[0];
    const float* key_in = (const float*)d_in[1];
    const float* value  = (const float*)d_in[2];
    const int*   mask   = (const int*)  d_in[3];
    const float* Wq = (const float*)d_in[4];
    const float* bq = (const float*)d_in[5];
    const float* Wk = (const float*)d_in[6];
    const float* bk = (const float*)d_in[7];
    const float* Wv = (const float*)d_in[8];
    const float* bv = (const float*)d_in[9];
    const float* Wo = (const float*)d_in[10];
    const float* bo = (const float*)d_in[11];
    float* out = (float*)d_out;

    __nv_bfloat16 *ah, *al;
    uint32_t* mbp;
    cudaGetSymbolAddress((void**)&ah, g_ah);
    cudaGetSymbolAddress((void**)&al, g_al);
    cudaGetSymbolAddress((void**)&mbp, g_mb);

    cudaFuncSetAttribute(tgemm<0>, cudaFuncAttributeMaxDynamicSharedMemorySize, GEMM_SMEM);
    cudaFuncSetAttribute(tgemm<1>, cudaFuncAttributeMaxDynamicSharedMemorySize, GEMM_SMEM);
    cudaFuncSetAttribute(flash, cudaFuncAttributeMaxDynamicSharedMemorySize, FLASH_SMEM);

    // mask pack
    maskpack_kernel<<<(Bsz * Ssz * Ssz) / 256, 256>>>(mask, mbp);
    // fused conversions
    dim3 wgrid((Dm * Dm / 4) / 256, 1, 4);
    cvtW_kernel<<<wgrid, 256>>>(Wq, Wk, Wv, Wo);
    dim3 agrid((int)((MD / 4) / 256), 1, 3);
    cvtA_kernel<<<agrid, 256>>>(query, key_in, value);
    // fused Q/K/V projections
    dim3 pgrid(Dm / 128, 8192 / 128, 3);
    tgemm<1><<<pgrid, 256, GEMM_SMEM>>>(bq, bk, bv, nullptr);
    // attention (x hi/lo -> activation slot 0)
    dim3 fgrid(Ssz / FQ, Hh, Bsz);
    flash<<<fgrid, 256, FLASH_SMEM>>>(mbp, ah, al);
    // output projection
    dim3 ogrid(Dm / 128, 8192 / 128);
    tgemm<0><<<ogrid, 256, GEMM_SMEM>>>(bo, nullptr, nullptr, out);
}

// round 7
// speedup vs baseline: 6.4061x; 1.0096x over previous
#include <cuda_runtime.h>
#include <cuda_bf16.h>
#include <math_constants.h>
#include <cstdint>

#define Bsz 4
#define Ssz 2048
#define Dm  1024
#define Hh  16
#define Dk  64
#define BH  (Bsz * Hh)
#define MD  ((size_t)8192 * 1024)
#define DD  ((size_t)1024 * 1024)

// ---------------- scratch (device globals; no allocation allowed) ----------
__device__ __align__(1024) __nv_bfloat16 g_qh[MD];
__device__ __align__(1024) __nv_bfloat16 g_ql[MD];
__device__ __align__(1024) __nv_bfloat16 g_kh[MD];
__device__ __align__(1024) __nv_bfloat16 g_kl[MD];
__device__ __align__(1024) __nv_bfloat16 g_vh[MD];
__device__ __align__(1024) __nv_bfloat16 g_vl[MD];
__device__ __align__(1024) __nv_bfloat16 g_ah[3 * MD];   // activations hi (q,k,v); slot0 reused for x
__device__ __align__(1024) __nv_bfloat16 g_al[3 * MD];
__device__ __align__(1024) __nv_bfloat16 g_wh[4 * DD];   // weights hi (Wq,Wk,Wv,Wo)
__device__ __align__(1024) __nv_bfloat16 g_wl[4 * DD];
__device__ __align__(1024) uint32_t g_mb[(size_t)Bsz * Ssz * (Ssz / 32)];

// ---------------- PTX helpers ----------------------------------------------
__device__ __forceinline__ uint32_t smem_u32(const void* p) {
    uint32_t a;
    asm("{ .reg .u64 t; cvta.to.shared.u64 t, %1; cvt.u32.u64 %0, t; }" : "=r"(a) : "l"(p));
    return a;
}
__device__ __forceinline__ void cp16(uint32_t dst, const void* src) {
    asm volatile("cp.async.cg.shared.global [%0], [%1], 16;" :: "r"(dst), "l"(src));
}
__device__ __forceinline__ void cp_commit() { asm volatile("cp.async.commit_group;"); }
__device__ __forceinline__ void cp_wait0()  { asm volatile("cp.async.wait_group 0;"); }

__device__ __forceinline__ void ldsm4(uint32_t* r, uint32_t a) {
    asm volatile("ldmatrix.sync.aligned.m8n8.x4.shared.b16 {%0,%1,%2,%3}, [%4];"
                 : "=r"(r[0]), "=r"(r[1]), "=r"(r[2]), "=r"(r[3]) : "r"(a));
}
__device__ __forceinline__ void ldsm4t(uint32_t* r, uint32_t a) {
    asm volatile("ldmatrix.sync.aligned.m8n8.x4.trans.shared.b16 {%0,%1,%2,%3}, [%4];"
                 : "=r"(r[0]), "=r"(r[1]), "=r"(r[2]), "=r"(r[3]) : "r"(a));
}
__device__ __forceinline__ void mma16816(float* d, const uint32_t* a, const uint32_t* b) {
    asm volatile("mma.sync.aligned.m16n8k16.row.col.f32.bf16.bf16.f32 "
                 "{%0,%1,%2,%3}, {%4,%5,%6,%7}, {%8,%9}, {%0,%1,%2,%3};"
                 : "+f"(d[0]), "+f"(d[1]), "+f"(d[2]), "+f"(d[3])
                 : "r"(a[0]), "r"(a[1]), "r"(a[2]), "r"(a[3]), "r"(b[0]), "r"(b[1]));
}
__device__ __forceinline__ uint32_t pack_bf16(float lo, float hi) {
    uint32_t r;
    asm("cvt.rn.bf16x2.f32 %0, %1, %2;" : "=r"(r) : "f"(hi), "f"(lo));
    return r;
}
__device__ __forceinline__ void split2(float v0, float v1, uint32_t& hp, uint32_t& lp) {
    hp = pack_bf16(v0, v1);
    __nv_bfloat162 h2 = *reinterpret_cast<__nv_bfloat162*>(&hp);
    float r0 = v0 - __bfloat162float(h2.x);
    float r1 = v1 - __bfloat162float(h2.y);
    lp = pack_bf16(r0, r1);
}
__device__ __forceinline__ float qmax(float v) {
    v = fmaxf(v, __shfl_xor_sync(0xffffffffu, v, 1));
    v = fmaxf(v, __shfl_xor_sync(0xffffffffu, v, 2));
    return v;
}
__device__ __forceinline__ float qsum(float v) {
    v += __shfl_xor_sync(0xffffffffu, v, 1);
    v += __shfl_xor_sync(0xffffffffu, v, 2);
    return v;
}

// ---------------- fused fp32 -> bf16 hi/lo conversions ----------------------
__global__ __launch_bounds__(256)
void cvtW_kernel(const float* __restrict__ w0, const float* __restrict__ w1,
                 const float* __restrict__ w2, const float* __restrict__ w3)
{
    const int z = blockIdx.z;
    const float* src = (z == 0) ? w0 : (z == 1) ? w1 : (z == 2) ? w2 : w3;
    __nv_bfloat16* hi = g_wh + (size_t)z * DD;
    __nv_bfloat16* lo = g_wl + (size_t)z * DD;
    const int i = blockIdx.x * 256 + threadIdx.x;
    float4 v = ((const float4*)src)[i];
    uint32_t h0, l0, h1, l1;
    split2(v.x, v.y, h0, l0);
    split2(v.z, v.w, h1, l1);
    ((uint2*)hi)[i] = make_uint2(h0, h1);
    ((uint2*)lo)[i] = make_uint2(l0, l1);
}

__global__ __launch_bounds__(256)
void cvtA_kernel(const float* __restrict__ a0, const float* __restrict__ a1,
                 const float* __restrict__ a2)
{
    const int z = blockIdx.z;
    const float* src = (z == 0) ? a0 : (z == 1) ? a1 : a2;
    __nv_bfloat16* hi = g_ah + (size_t)z * MD;
    __nv_bfloat16* lo = g_al + (size_t)z * MD;
    const int i = blockIdx.x * 256 + threadIdx.x;
    float4 v = ((const float4*)src)[i];
    uint32_t h0, l0, h1, l1;
    split2(v.x, v.y, h0, l0);
    split2(v.z, v.w, h1, l1);
    ((uint2*)hi)[i] = make_uint2(h0, h1);
    ((uint2*)lo)[i] = make_uint2(l0, l1);
}

// ---------------- mask -> bitmask pack --------------------------------------
__global__ __launch_bounds__(256)
void maskpack_kernel(const int* __restrict__ mask, uint32_t* __restrict__ bits)
{
    const int i = blockIdx.x * 256 + threadIdx.x;
    const uint32_t b = __ballot_sync(0xffffffffu, mask[i] != 0);
    if ((threadIdx.x & 31) == 0) bits[i >> 5] = b;
}

// ---------------- tensor-core split-bf16 GEMM (3-pass) ----------------------
#define GSTRIDE 80
#define GARR    10240
#define GSTAGE  40960
#define GEMM_SMEM (2 * GSTAGE)

__device__ __forceinline__ void gemm_load(uint32_t sb, int stage, int c, int tid,
                                          int m0, int n0,
                                          const __nv_bfloat16* Ah, const __nv_bfloat16* Al,
                                          const __nv_bfloat16* Wh, const __nv_bfloat16* Wl)
{
#pragma unroll
    for (int it = 0; it < 8; it++) {
        const int flat = it * 256 + tid;
        const int arr = flat >> 9, rem = flat & 511;
        const int row = rem >> 2, seg = rem & 3;
        const __nv_bfloat16* src = (arr == 0) ? Ah : (arr == 1) ? Al : (arr == 2) ? Wh : Wl;
        const int gbase = (arr < 2) ? m0 : n0;
        cp16(sb + stage * GSTAGE + arr * GARR + row * GSTRIDE + seg * 16,
             src + (size_t)(gbase + row) * Dm + c * 32 + seg * 8);
    }
    cp_commit();
}

// MODE 0: output projection -> fp32 C.  MODE 1: per-z projection -> head-split bf16 hi/lo.
template <int MODE>
__global__ __launch_bounds__(256, 2)
void tgemm(const float* __restrict__ b0p, const float* __restrict__ b1p,
           const float* __restrict__ b2p, float* __restrict__ C)
{
    extern __shared__ char smem[];
    const uint32_t sb = smem_u32(smem);
    const int tid = threadIdx.x;
    const int lane = tid & 31, w = tid >> 5;
    const int wm = w >> 1, wn = w & 1;
    const int m0 = blockIdx.y * 128, n0 = blockIdx.x * 128;
    const int z = (MODE == 1) ? blockIdx.z : 3;

    const __nv_bfloat16* Ah = g_ah + ((MODE == 1) ? (size_t)z * MD : 0);
    const __nv_bfloat16* Al = g_al + ((MODE == 1) ? (size_t)z * MD : 0);
    const __nv_bfloat16* Wh = g_wh + (size_t)z * DD;
    const __nv_bfloat16* Wl = g_wl + (size_t)z * DD;
    const float* bias = (MODE == 0) ? b0p : (z == 0) ? b0p : (z == 1) ? b1p : b2p;
    __nv_bfloat16* Oh = (MODE == 1) ? ((z == 0) ? g_qh : (z == 1) ? g_kh : g_vh) : nullptr;
    __nv_bfloat16* Ol = (MODE == 1) ? ((z == 0) ? g_ql : (z == 1) ? g_kl : g_vl) : nullptr;

    float acc[2][8][4];
#pragma unroll
    for (int mt = 0; mt < 2; mt++)
#pragma unroll
        for (int nt = 0; nt < 8; nt++)
#pragma unroll
            for (int r = 0; r < 4; r++) acc[mt][nt][r] = 0.f;

    gemm_load(sb, 0, 0, tid, m0, n0, Ah, Al, Wh, Wl);

    for (int c = 0; c < 32; c++) {
        cp_wait0();
        __syncthreads();
        if (c + 1 < 32) gemm_load(sb, (c + 1) & 1, c + 1, tid, m0, n0, Ah, Al, Wh, Wl);
        const uint32_t st = sb + (c & 1) * GSTAGE;
#pragma unroll
        for (int kt = 0; kt < 2; kt++) {
            uint32_t a_h[2][4], a_l[2][4];
#pragma unroll
            for (int mt = 0; mt < 2; mt++) {
                const uint32_t ra = st +
                    (uint32_t)(wm * 32 + mt * 16 + ((lane >> 3) & 1) * 8 + (lane & 7)) * GSTRIDE +
                    kt * 32 + (lane >> 4) * 16;
                ldsm4(a_h[mt], ra);
                ldsm4(a_l[mt], ra + GARR);
            }
#pragma unroll
            for (int hf = 0; hf < 2; hf++) {
                uint32_t b_h[2][4], b_l[2][4];
#pragma unroll
                for (int j = 0; j < 2; j++) {
                    const int nt2 = hf * 2 + j;
                    const uint32_t rb = st + 2 * GARR +
                        (uint32_t)(wn * 64 + nt2 * 16 + (lane >> 4) * 8 + (lane & 7)) * GSTRIDE +
                        kt * 32 + ((lane >> 3) & 1) * 16;
                    ldsm4(b_h[j], rb);
                    ldsm4(b_l[j], rb + GARR);
                }
                // pass sweeps: 8 distinct accumulators per sweep (reuse distance 8)
#pragma unroll
                for (int mt = 0; mt < 2; mt++)
#pragma unroll
                    for (int j = 0; j < 2; j++) {
                        mma16816(acc[mt][(hf * 2 + j) * 2],     a_h[mt], b_h[j]);
                        mma16816(acc[mt][(hf * 2 + j) * 2 + 1], a_h[mt], b_h[j] + 2);
                    }
#pragma unroll
                for (int mt = 0; mt < 2; mt++)
#pragma unroll
                    for (int j = 0; j < 2; j++) {
                        mma16816(acc[mt][(hf * 2 + j) * 2],     a_h[mt], b_l[j]);
                        mma16816(acc[mt][(hf * 2 + j) * 2 + 1], a_h[mt], b_l[j] + 2);
                    }
#pragma unroll
                for (int mt = 0; mt < 2; mt++)
#pragma unroll
                    for (int j = 0; j < 2; j++) {
                        mma16816(acc[mt][(hf * 2 + j) * 2],     a_l[mt], b_h[j]);
                        mma16816(acc[mt][(hf * 2 + j) * 2 + 1], a_l[mt], b_h[j] + 2);
                    }
            }
        }
    }

    const int grp = lane >> 2, qc = lane & 3;
#pragma unroll
    for (int mt = 0; mt < 2; mt++) {
#pragma unroll
        for (int nt = 0; nt < 8; nt++) {
            const int row = m0 + wm * 32 + mt * 16 + grp;
            const int col = n0 + wn * 64 + nt * 8 + qc * 2;
            const float b0 = bias[col], b1 = bias[col + 1];
            const float v0 = acc[mt][nt][0] + b0, v1 = acc[mt][nt][1] + b1;
            const float v2 = acc[mt][nt][2] + b0, v3 = acc[mt][nt][3] + b1;
            if (MODE == 0) {
                *(float2*)&C[(size_t)row * Dm + col]       = make_float2(v0, v1);
                *(float2*)&C[(size_t)(row + 8) * Dm + col] = make_float2(v2, v3);
            } else {
                const int hh = col >> 6, dk = col & 63;
                {
                    const int bb = row >> 11, s = row & 2047;
                    const size_t idx = (((size_t)(bb * Hh + hh)) * Ssz + s) * Dk + dk;
                    uint32_t hp, lp; split2(v0, v1, hp, lp);
                    *(uint32_t*)&Oh[idx] = hp; *(uint32_t*)&Ol[idx] = lp;
                }
                {
                    const int r2 = row + 8;
                    const int bb = r2 >> 11, s = r2 & 2047;
                    const size_t idx = (((size_t)(bb * Hh + hh)) * Ssz + s) * Dk + dk;
                    uint32_t hp, lp; split2(v2, v3, hp, lp);
                    *(uint32_t*)&Oh[idx] = hp; *(uint32_t*)&Ol[idx] = lp;
                }
            }
        }
    }
}

// ---------------- flash attention (3-pass QK, 3-pass PV, reordered) ---------
#define FQ 128
#define FK 64
#define FSTR 144
#define QH_OFF 0
#define QL_OFF 18432
#define KV_OFF 36864
#define KVST   36864
#define KL_O 9216
#define VH_O 18432
#define VL_O 27648
#define FLASH_SMEM 110592   // 108 KB -> 2 CTAs/SM

__device__ __forceinline__ void flash_load_kv(uint32_t sb, int j, int tid, size_t bh)
{
#pragma unroll
    for (int it = 0; it < 8; it++) {
        const int flat = it * 256 + tid;
        const int arr = flat >> 9, rem = flat & 511;
        const int row = rem >> 3, seg = rem & 7;
        const __nv_bfloat16* src = (arr == 0) ? g_kh : (arr == 1) ? g_kl : (arr == 2) ? g_vh : g_vl;
        cp16(sb + KV_OFF + (j & 1) * KVST + arr * 9216 + row * FSTR + seg * 16,
             src + (bh * Ssz + j * FK + row) * Dk + seg * 8);
    }
    cp_commit();
}

__global__ __launch_bounds__(256, 2)
void flash(const uint32_t* __restrict__ mb,
           __nv_bfloat16* __restrict__ xh, __nv_bfloat16* __restrict__ xl)
{
    extern __shared__ char smem[];
    const uint32_t sb = smem_u32(smem);
    const int tid = threadIdx.x, lane = tid & 31, w = tid >> 5;
    const int b = blockIdx.z, h = blockIdx.y, q0 = blockIdx.x * FQ;
    const size_t bh = (size_t)(b * Hh + h);
    const int grp = lane >> 2, qc = lane & 3;
    const int row_a = q0 + w * 16 + grp;

    flash_load_kv(sb, 0, tid, bh);
#pragma unroll
    for (int it = 0; it < 8; it++) {
        const int flat = it * 256 + tid;
        const int arr = flat >> 10, rem = flat & 1023;
        const int row = rem >> 3, seg = rem & 7;
        const __nv_bfloat16* src = (arr == 0) ? g_qh : g_ql;
        cp16(sb + arr * QL_OFF + row * FSTR + seg * 16,
             src + (bh * Ssz + q0 + row) * Dk + seg * 8);
    }
    cp_commit();
    cp_wait0();
    __syncthreads();

    // hoist loop-invariant Q-hi fragments
    const uint32_t qrow = (uint32_t)(w * 16 + ((lane >> 3) & 1) * 8 + (lane & 7)) * FSTR +
                          (lane >> 4) * 16;
    uint32_t qfh[4][4];
#pragma unroll
    for (int kt = 0; kt < 4; kt++) ldsm4(qfh[kt], sb + QH_OFF + qrow + kt * 32);

    float acc_o[8][4];
#pragma unroll
    for (int nt = 0; nt < 8; nt++)
#pragma unroll
        for (int r = 0; r < 4; r++) acc_o[nt][r] = 0.f;
    float m_a = -CUDART_INF_F, m_b = -CUDART_INF_F, l_a = 0.f, l_b = 0.f;

    const uint32_t* mrow_a = mb + ((size_t)b * Ssz + row_a) * (Ssz / 32);
    const uint32_t* mrow_b = mrow_a + 8 * (Ssz / 32);

    const int NJT = Ssz / FK;   // 32
    for (int jt = 0; jt < NJT; jt++) {
        const uint2 wa = *(const uint2*)(mrow_a + jt * 2);
        const uint2 wb = *(const uint2*)(mrow_b + jt * 2);
        if (jt > 0) { cp_wait0(); __syncthreads(); }
        if (jt + 1 < NJT) flash_load_kv(sb, jt + 1, tid, bh);
        const uint32_t st = sb + KV_OFF + (jt & 1) * KVST;

        // ---- QK^T (3-pass, pass-swept over 4 accumulators per half) ----
        float s[8][4];
#pragma unroll
        for (int nt = 0; nt < 8; nt++)
#pragma unroll
            for (int r = 0; r < 4; r++) s[nt][r] = 0.f;
#pragma unroll
        for (int kt = 0; kt < 4; kt++) {
            uint32_t a_l[4];
            ldsm4(a_l, sb + QL_OFF + qrow + kt * 32);
#pragma unroll
            for (int hf = 0; hf < 2; hf++) {
                uint32_t b_h[2][4], b_l[2][4];
#pragma unroll
                for (int j = 0; j < 2; j++) {
                    const int nt2 = hf * 2 + j;
                    const uint32_t rb = st +
                        (uint32_t)(nt2 * 16 + (lane >> 4) * 8 + (lane & 7)) * FSTR +
                        kt * 32 + ((lane >> 3) & 1) * 16;
                    ldsm4(b_h[j], rb);
                    ldsm4(b_l[j], rb + KL_O);
                }
#pragma unroll
                for (int j = 0; j < 2; j++) {
                    mma16816(s[(hf * 2 + j) * 2],     qfh[kt], b_h[j]);
                    mma16816(s[(hf * 2 + j) * 2 + 1], qfh[kt], b_h[j] + 2);
                }
#pragma unroll
                for (int j = 0; j < 2; j++) {
                    mma16816(s[(hf * 2 + j) * 2],     qfh[kt], b_l[j]);
                    mma16816(s[(hf * 2 + j) * 2 + 1], qfh[kt], b_l[j] + 2);
                }
#pragma unroll
                for (int j = 0; j < 2; j++) {
                    mma16816(s[(hf * 2 + j) * 2],     a_l, b_h[j]);
                    mma16816(s[(hf * 2 + j) * 2 + 1], a_l, b_h[j] + 2);
                }
            }
        }

        // ---- scale + mask + online softmax ----
        float ra = -CUDART_INF_F, rbx = -CUDART_INF_F;
#pragma unroll
        for (int nt = 0; nt < 8; nt++) {
            const int kk = nt * 8 + qc * 2;
            const uint32_t wA = (nt < 4) ? wa.x : wa.y;
            const uint32_t wB = (nt < 4) ? wb.x : wb.y;
            const int bit = kk & 31;
            s[nt][0] = ((wA >> bit) & 1)       ? s[nt][0] * 0.125f : -1e9f;
            s[nt][1] = ((wA >> (bit + 1)) & 1) ? s[nt][1] * 0.125f : -1e9f;
            s[nt][2] = ((wB >> bit) & 1)       ? s[nt][2] * 0.125f : -1e9f;
            s[nt][3] = ((wB >> (bit + 1)) & 1) ? s[nt][3] * 0.125f : -1e9f;
            ra  = fmaxf(ra,  fmaxf(s[nt][0], s[nt][1]));
            rbx = fmaxf(rbx, fmaxf(s[nt][2], s[nt][3]));
        }
        ra = qmax(ra); rbx = qmax(rbx);
        const float mna = fmaxf(m_a, ra), mnb = fmaxf(m_b, rbx);
        const float ca = __expf(m_a - mna), cb = __expf(m_b - mnb);
        float suma = 0.f, sumb = 0.f;
#pragma unroll
        for (int nt = 0; nt < 8; nt++) {
            s[nt][0] = __expf(s[nt][0] - mna);
            s[nt][1] = __expf(s[nt][1] - mna);
            s[nt][2] = __expf(s[nt][2] - mnb);
            s[nt][3] = __expf(s[nt][3] - mnb);
            suma += s[nt][0] + s[nt][1];
            sumb += s[nt][2] + s[nt][3];
        }
        l_a = l_a * ca + qsum(suma);
        l_b = l_b * cb + qsum(sumb);
#pragma unroll
        for (int nt = 0; nt < 8; nt++) {
            acc_o[nt][0] *= ca; acc_o[nt][1] *= ca;
            acc_o[nt][2] *= cb; acc_o[nt][3] *= cb;
        }
        m_a = mna; m_b = mnb;

        // ---- P @ V (3-pass, P fragments in registers, pass-swept) ----
#pragma unroll
        for (int kt2 = 0; kt2 < 4; kt2++) {
            uint32_t p_h[4], p_l[4];
            split2(s[2 * kt2][0],     s[2 * kt2][1],     p_h[0], p_l[0]);
            split2(s[2 * kt2][2],     s[2 * kt2][3],     p_h[1], p_l[1]);
            split2(s[2 * kt2 + 1][0], s[2 * kt2 + 1][1], p_h[2], p_l[2]);
            split2(s[2 * kt2 + 1][2], s[2 * kt2 + 1][3], p_h[3], p_l[3]);
#pragma unroll
            for (int hf = 0; hf < 2; hf++) {
                uint32_t v_h[2][4], v_l[2][4];
#pragma unroll
                for (int j = 0; j < 2; j++) {
                    const int nd2 = hf * 2 + j;
                    const uint32_t vb = st + VH_O +
                        (uint32_t)(kt2 * 16 + ((lane >> 3) & 1) * 8 + (lane & 7)) * FSTR +
                        nd2 * 32 + (lane >> 4) * 16;
                    ldsm4t(v_h[j], vb);
                    ldsm4t(v_l[j], vb + (VL_O - VH_O));
                }
#pragma unroll
                for (int j = 0; j < 2; j++) {
                    mma16816(acc_o[(hf * 2 + j) * 2],     p_h, v_h[j]);
                    mma16816(acc_o[(hf * 2 + j) * 2 + 1], p_h, v_h[j] + 2);
                }
#pragma unroll
                for (int j = 0; j < 2; j++) {
                    mma16816(acc_o[(hf * 2 + j) * 2],     p_h, v_l[j]);
                    mma16816(acc_o[(hf * 2 + j) * 2 + 1], p_h, v_l[j] + 2);
                }
#pragma unroll
                for (int j = 0; j < 2; j++) {
                    mma16816(acc_o[(hf * 2 + j) * 2],     p_l, v_h[j]);
                    mma16816(acc_o[(hf * 2 + j) * 2 + 1], p_l, v_h[j] + 2);
                }
            }
        }
    }

    // epilogue
    const float inva = 1.f / l_a, invb = 1.f / l_b;
#pragma unroll
    for (int nt = 0; nt < 8; nt++) {
        const int col = h * Dk + nt * 8 + qc * 2;
        uint32_t hp, lp;
        split2(acc_o[nt][0] * inva, acc_o[nt][1] * inva, hp, lp);
        size_t idx = ((size_t)b * Ssz + row_a) * Dm + col;
        *(uint32_t*)&xh[idx] = hp; *(uint32_t*)&xl[idx] = lp;
        split2(acc_o[nt][2] * invb, acc_o[nt][3] * invb, hp, lp);
        idx = ((size_t)b * Ssz + row_a + 8) * Dm + col;
        *(uint32_t*)&xh[idx] = hp; *(uint32_t*)&xl[idx] = lp;
    }
}

// ---------------- launch ----------------------------------------------------
extern "C" void kernel_launch(void* const* d_in, const int* in_sizes, int n_in,
                              void* d_out, int out_size)
{
    (void)in_sizes; (void)n_in; (void)out_size;
    const float* query  = (const float*)d_in[0];
    const float* key_in = (const float*)d_in[1];
    const float* value  = (const float*)d_in[2];
    const int*   mask   = (const int*)  d_in[3];
    const float* Wq = (const float*)d_in[4];
    const float* bq = (const float*)d_in[5];
    const float* Wk = (const float*)d_in[6];
    const float* bk = (const float*)d_in[7];
    const float* Wv = (const float*)d_in[8];
    const float* bv = (const float*)d_in[9];
    const float* Wo = (const float*)d_in[10];
    const float* bo = (const float*)d_in[11];
    float* out = (float*)d_out;

    __nv_bfloat16 *ah, *al;
    uint32_t* mbp;
    cudaGetSymbolAddress((void**)&ah, g_ah);
    cudaGetSymbolAddress((void**)&al, g_al);
    cudaGetSymbolAddress((void**)&mbp, g_mb);

    cudaFuncSetAttribute(tgemm<0>, cudaFuncAttributeMaxDynamicSharedMemorySize, GEMM_SMEM);
    cudaFuncSetAttribute(tgemm<1>, cudaFuncAttributeMaxDynamicSharedMemorySize, GEMM_SMEM);
    cudaFuncSetAttribute(flash, cudaFuncAttributeMaxDynamicSharedMemorySize, FLASH_SMEM);

    // mask pack
    maskpack_kernel<<<(Bsz * Ssz * Ssz) / 256, 256>>>(mask, mbp);
    // fused conversions
    dim3 wgrid((Dm * Dm / 4) / 256, 1, 4);
    cvtW_kernel<<<wgrid, 256>>>(Wq, Wk, Wv, Wo);
    dim3 agrid((int)((MD / 4) / 256), 1, 3);
    cvtA_kernel<<<agrid, 256>>>(query, key_in, value);
    // fused Q/K/V projections
    dim3 pgrid(Dm / 128, 8192 / 128, 3);
    tgemm<1><<<pgrid, 256, GEMM_SMEM>>>(bq, bk, bv, nullptr);
    // attention (x hi/lo -> activation slot 0)
    dim3 fgrid(Ssz / FQ, Hh, Bsz);
    flash<<<fgrid, 256, FLASH_SMEM>>>(mbp, ah, al);
    // output projection
    dim3 ogrid(Dm / 128, 8192 / 128);
    tgemm<0><<<ogrid, 256, GEMM_SMEM>>>(bo, nullptr, nullptr, out);
}

// round 8
// speedup vs baseline: 8.9430x; 1.3960x over previous
#include <cuda_runtime.h>
#include <cuda_fp16.h>
#include <math_constants.h>
#include <cstdint>

#define Bsz 4
#define Ssz 2048
#define Dm  1024
#define Hh  16
#define Dk  64
#define BH  (Bsz * Hh)
#define MD  ((size_t)8192 * 1024)
#define DD  ((size_t)1024 * 1024)

// ---------------- scratch (device globals; no allocation allowed) ----------
__device__ __align__(1024) __half g_qh[MD];            // Q hi (head-split)
__device__ __align__(1024) __half g_kh[MD];            // K hi
__device__ __align__(1024) __half g_kl[MD];            // K lo
__device__ __align__(1024) __half g_vh[MD];            // V hi
__device__ __align__(1024) __half g_ah[3 * MD];        // activations hi (q,k,v); slot0 reused for x
__device__ __align__(1024) __half g_wh[4 * DD];        // weights hi (Wq,Wk,Wv,Wo)
__device__ __align__(1024) __half g_wl[4 * DD];        // weights lo
__device__ __align__(1024) uint32_t g_mb[(size_t)Bsz * Ssz * (Ssz / 32)];

// ---------------- PTX helpers ----------------------------------------------
__device__ __forceinline__ uint32_t smem_u32(const void* p) {
    uint32_t a;
    asm("{ .reg .u64 t; cvta.to.shared.u64 t, %1; cvt.u32.u64 %0, t; }" : "=r"(a) : "l"(p));
    return a;
}
__device__ __forceinline__ void cp16(uint32_t dst, const void* src) {
    asm volatile("cp.async.cg.shared.global [%0], [%1], 16;" :: "r"(dst), "l"(src));
}
__device__ __forceinline__ void cp_commit() { asm volatile("cp.async.commit_group;"); }
__device__ __forceinline__ void cp_wait0()  { asm volatile("cp.async.wait_group 0;"); }

__device__ __forceinline__ void ldsm4(uint32_t* r, uint32_t a) {
    asm volatile("ldmatrix.sync.aligned.m8n8.x4.shared.b16 {%0,%1,%2,%3}, [%4];"
                 : "=r"(r[0]), "=r"(r[1]), "=r"(r[2]), "=r"(r[3]) : "r"(a));
}
__device__ __forceinline__ void ldsm4t(uint32_t* r, uint32_t a) {
    asm volatile("ldmatrix.sync.aligned.m8n8.x4.trans.shared.b16 {%0,%1,%2,%3}, [%4];"
                 : "=r"(r[0]), "=r"(r[1]), "=r"(r[2]), "=r"(r[3]) : "r"(a));
}
__device__ __forceinline__ void mma16816(float* d, const uint32_t* a, const uint32_t* b) {
    asm volatile("mma.sync.aligned.m16n8k16.row.col.f32.f16.f16.f32 "
                 "{%0,%1,%2,%3}, {%4,%5,%6,%7}, {%8,%9}, {%0,%1,%2,%3};"
                 : "+f"(d[0]), "+f"(d[1]), "+f"(d[2]), "+f"(d[3])
                 : "r"(a[0]), "r"(a[1]), "r"(a[2]), "r"(a[3]), "r"(b[0]), "r"(b[1]));
}
__device__ __forceinline__ uint32_t pack_f16(float lo, float hi) {
    uint32_t r;
    asm("cvt.rn.f16x2.f32 %0, %1, %2;" : "=r"(r) : "f"(hi), "f"(lo));
    return r;
}
__device__ __forceinline__ void split2(float v0, float v1, uint32_t& hp, uint32_t& lp) {
    hp = pack_f16(v0, v1);
    __half2 h2 = *reinterpret_cast<__half2*>(&hp);
    float r0 = v0 - __half2float(h2.x);
    float r1 = v1 - __half2float(h2.y);
    lp = pack_f16(r0, r1);
}
__device__ __forceinline__ float qmax(float v) {
    v = fmaxf(v, __shfl_xor_sync(0xffffffffu, v, 1));
    v = fmaxf(v, __shfl_xor_sync(0xffffffffu, v, 2));
    return v;
}
__device__ __forceinline__ float qsum(float v) {
    v += __shfl_xor_sync(0xffffffffu, v, 1);
    v += __shfl_xor_sync(0xffffffffu, v, 2);
    return v;
}

// ---------------- fused fp32 -> fp16 conversions ----------------------------
__global__ __launch_bounds__(256)
void cvtW_kernel(const float* __restrict__ w0, const float* __restrict__ w1,
                 const float* __restrict__ w2, const float* __restrict__ w3)
{
    const int z = blockIdx.z;
    const float* src = (z == 0) ? w0 : (z == 1) ? w1 : (z == 2) ? w2 : w3;
    __half* hi = g_wh + (size_t)z * DD;
    __half* lo = g_wl + (size_t)z * DD;
    const int i = blockIdx.x * 256 + threadIdx.x;
    float4 v = ((const float4*)src)[i];
    uint32_t h0, l0, h1, l1;
    split2(v.x, v.y, h0, l0);
    split2(v.z, v.w, h1, l1);
    ((uint2*)hi)[i] = make_uint2(h0, h1);
    ((uint2*)lo)[i] = make_uint2(l0, l1);
}

__global__ __launch_bounds__(256)
void cvtA_kernel(const float* __restrict__ a0, const float* __restrict__ a1,
                 const float* __restrict__ a2)
{
    const int z = blockIdx.z;
    const float* src = (z == 0) ? a0 : (z == 1) ? a1 : a2;
    __half* hi = g_ah + (size_t)z * MD;
    const int i = blockIdx.x * 256 + threadIdx.x;
    float4 v = ((const float4*)src)[i];
    ((uint2*)hi)[i] = make_uint2(pack_f16(v.x, v.y), pack_f16(v.z, v.w));
}

// ---------------- mask -> bitmask pack --------------------------------------
__global__ __launch_bounds__(256)
void maskpack_kernel(const int* __restrict__ mask, uint32_t* __restrict__ bits)
{
    const int i = blockIdx.x * 256 + threadIdx.x;
    const uint32_t b = __ballot_sync(0xffffffffu, mask[i] != 0);
    if ((threadIdx.x & 31) == 0) bits[i >> 5] = b;
}

// ---------------- tensor-core 2-pass fp16 GEMM ------------------------------
// C = (Ah)·(Wh+Wl)^T + bias; 128x128 CTA tile, BK=32, double-buffered.
#define GSTRIDE 80
#define GARR    10240
#define GSTAGE  30720            // 3 arrays (Ah, Wh, Wl)
#define GEMM_SMEM (2 * GSTAGE)

__device__ __forceinline__ void gemm_load(uint32_t sb, int stage, int c, int tid,
                                          int m0, int n0,
                                          const __half* Ah, const __half* Wh, const __half* Wl)
{
#pragma unroll
    for (int it = 0; it < 6; it++) {
        const int flat = it * 256 + tid;                 // 0..1535
        const int arr = flat / 512, rem = flat & 511;
        const int row = rem >> 2, seg = rem & 3;
        const __half* src = (arr == 0) ? Ah : (arr == 1) ? Wh : Wl;
        const int gbase = (arr == 0) ? m0 : n0;
        cp16(sb + stage * GSTAGE + arr * GARR + row * GSTRIDE + seg * 16,
             src + (size_t)(gbase + row) * Dm + c * 32 + seg * 8);
    }
    cp_commit();
}

// MODE 0: output projection -> fp32 C.  MODE 1: per-z projection -> head-split fp16.
template <int MODE>
__global__ __launch_bounds__(256, 2)
void tgemm(const float* __restrict__ b0p, const float* __restrict__ b1p,
           const float* __restrict__ b2p, float* __restrict__ C)
{
    extern __shared__ char smem[];
    const uint32_t sb = smem_u32(smem);
    const int tid = threadIdx.x;
    const int lane = tid & 31, w = tid >> 5;
    const int wm = w >> 1, wn = w & 1;
    const int m0 = blockIdx.y * 128, n0 = blockIdx.x * 128;
    const int z = (MODE == 1) ? blockIdx.z : 3;

    const __half* Ah = g_ah + ((MODE == 1) ? (size_t)z * MD : 0);
    const __half* Wh = g_wh + (size_t)z * DD;
    const __half* Wl = g_wl + (size_t)z * DD;
    const float* bias = (MODE == 0) ? b0p : (z == 0) ? b0p : (z == 1) ? b1p : b2p;
    __half* Oh = (MODE == 1) ? ((z == 0) ? g_qh : (z == 1) ? g_kh : g_vh) : nullptr;

    float acc[2][8][4];
#pragma unroll
    for (int mt = 0; mt < 2; mt++)
#pragma unroll
        for (int nt = 0; nt < 8; nt++)
#pragma unroll
            for (int r = 0; r < 4; r++) acc[mt][nt][r] = 0.f;

    gemm_load(sb, 0, 0, tid, m0, n0, Ah, Wh, Wl);

    for (int c = 0; c < 32; c++) {
        cp_wait0();
        __syncthreads();
        if (c + 1 < 32) gemm_load(sb, (c + 1) & 1, c + 1, tid, m0, n0, Ah, Wh, Wl);
        const uint32_t st = sb + (c & 1) * GSTAGE;
#pragma unroll
        for (int kt = 0; kt < 2; kt++) {
            uint32_t a_h[2][4];
#pragma unroll
            for (int mt = 0; mt < 2; mt++) {
                const uint32_t ra = st +
                    (uint32_t)(wm * 32 + mt * 16 + ((lane >> 3) & 1) * 8 + (lane & 7)) * GSTRIDE +
                    kt * 32 + (lane >> 4) * 16;
                ldsm4(a_h[mt], ra);
            }
#pragma unroll
            for (int hf = 0; hf < 2; hf++) {
                uint32_t b_h[2][4], b_l[2][4];
#pragma unroll
                for (int j = 0; j < 2; j++) {
                    const int nt2 = hf * 2 + j;
                    const uint32_t rb = st + GARR +
                        (uint32_t)(wn * 64 + nt2 * 16 + (lane >> 4) * 8 + (lane & 7)) * GSTRIDE +
                        kt * 32 + ((lane >> 3) & 1) * 16;
                    ldsm4(b_h[j], rb);
                    ldsm4(b_l[j], rb + GARR);
                }
#pragma unroll
                for (int mt = 0; mt < 2; mt++)
#pragma unroll
                    for (int j = 0; j < 2; j++) {
                        mma16816(acc[mt][(hf * 2 + j) * 2],     a_h[mt], b_h[j]);
                        mma16816(acc[mt][(hf * 2 + j) * 2 + 1], a_h[mt], b_h[j] + 2);
                    }
#pragma unroll
                for (int mt = 0; mt < 2; mt++)
#pragma unroll
                    for (int j = 0; j < 2; j++) {
                        mma16816(acc[mt][(hf * 2 + j) * 2],     a_h[mt], b_l[j]);
                        mma16816(acc[mt][(hf * 2 + j) * 2 + 1], a_h[mt], b_l[j] + 2);
                    }
            }
        }
    }

    const int grp = lane >> 2, qc = lane & 3;
#pragma unroll
    for (int mt = 0; mt < 2; mt++) {
#pragma unroll
        for (int nt = 0; nt < 8; nt++) {
            const int row = m0 + wm * 32 + mt * 16 + grp;
            const int col = n0 + wn * 64 + nt * 8 + qc * 2;
            const float b0 = bias[col], b1 = bias[col + 1];
            const float v0 = acc[mt][nt][0] + b0, v1 = acc[mt][nt][1] + b1;
            const float v2 = acc[mt][nt][2] + b0, v3 = acc[mt][nt][3] + b1;
            if (MODE == 0) {
                *(float2*)&C[(size_t)row * Dm + col]       = make_float2(v0, v1);
                *(float2*)&C[(size_t)(row + 8) * Dm + col] = make_float2(v2, v3);
            } else {
                const int hh = col >> 6, dk = col & 63;
#pragma unroll
                for (int half_i = 0; half_i < 2; half_i++) {
                    const int r2 = row + half_i * 8;
                    const int bb = r2 >> 11, s = r2 & 2047;
                    const size_t idx = (((size_t)(bb * Hh + hh)) * Ssz + s) * Dk + dk;
                    const float x0 = half_i ? v2 : v0, x1 = half_i ? v3 : v1;
                    if (z == 1) {          // K keeps hi+lo (QK 2-pass uses K-lo)
                        uint32_t hp, lp; split2(x0, x1, hp, lp);
                        *(uint32_t*)&Oh[idx] = hp;
                        *(uint32_t*)&g_kl[idx] = lp;
                    } else {               // Q, V: hi only
                        *(uint32_t*)&Oh[idx] = pack_f16(x0, x1);
                    }
                }
            }
        }
    }
}

// ---------------- flash attention: fp16, 2-pass QK, 2-pass PV ---------------
#define FQ 128
#define FK 64
#define FSTR 144
#define QH_OFF 0
#define KV_OFF 18432
#define KVST   27648            // per stage: kh, kl, vh (9216 each)
#define KL_O 9216
#define VH_O 18432
#define FLASH_SMEM 73728        // 72 KB -> 2 CTAs/SM

__device__ __forceinline__ void flash_load_kv(uint32_t sb, int j, int tid, size_t bh)
{
#pragma unroll
    for (int it = 0; it < 6; it++) {
        const int flat = it * 256 + tid;                 // 0..1535
        const int arr = flat / 512, rem = flat & 511;
        const int row = rem >> 3, seg = rem & 7;
        const __half* src = (arr == 0) ? g_kh : (arr == 1) ? g_kl : g_vh;
        cp16(sb + KV_OFF + (j & 1) * KVST + arr * 9216 + row * FSTR + seg * 16,
             src + (bh * Ssz + j * FK + row) * Dk + seg * 8);
    }
    cp_commit();
}

__global__ __launch_bounds__(256, 2)
void flash(const uint32_t* __restrict__ mb, __half* __restrict__ xh)
{
    extern __shared__ char smem[];
    const uint32_t sb = smem_u32(smem);
    const int tid = threadIdx.x, lane = tid & 31, w = tid >> 5;
    const int b = blockIdx.z, h = blockIdx.y, q0 = blockIdx.x * FQ;
    const size_t bh = (size_t)(b * Hh + h);
    const int grp = lane >> 2, qc = lane & 3;
    const int row_a = q0 + w * 16 + grp;

    flash_load_kv(sb, 0, tid, bh);
#pragma unroll
    for (int it = 0; it < 4; it++) {
        const int flat = it * 256 + tid;                 // 0..1023
        const int row = flat >> 3, seg = flat & 7;
        cp16(sb + QH_OFF + row * FSTR + seg * 16,
             g_qh + (bh * Ssz + q0 + row) * Dk + seg * 8);
    }
    cp_commit();
    cp_wait0();
    __syncthreads();

    // hoist loop-invariant Q-hi fragments
    const uint32_t qrow = (uint32_t)(w * 16 + ((lane >> 3) & 1) * 8 + (lane & 7)) * FSTR +
                          (lane >> 4) * 16;
    uint32_t qfh[4][4];
#pragma unroll
    for (int kt = 0; kt < 4; kt++) ldsm4(qfh[kt], sb + QH_OFF + qrow + kt * 32);

    float acc_o[8][4];
#pragma unroll
    for (int nt = 0; nt < 8; nt++)
#pragma unroll
        for (int r = 0; r < 4; r++) acc_o[nt][r] = 0.f;
    float m_a = -CUDART_INF_F, m_b = -CUDART_INF_F, l_a = 0.f, l_b = 0.f;

    const uint32_t* mrow_a = mb + ((size_t)b * Ssz + row_a) * (Ssz / 32);
    const uint32_t* mrow_b = mrow_a + 8 * (Ssz / 32);

    const int NJT = Ssz / FK;   // 32
    for (int jt = 0; jt < NJT; jt++) {
        const uint2 wa = *(const uint2*)(mrow_a + jt * 2);
        const uint2 wb = *(const uint2*)(mrow_b + jt * 2);
        if (jt > 0) { cp_wait0(); __syncthreads(); }
        if (jt + 1 < NJT) flash_load_kv(sb, jt + 1, tid, bh);
        const uint32_t st = sb + KV_OFF + (jt & 1) * KVST;

        // ---- QK^T: Qh·Kh + Qh·Kl (2-pass) ----
        float s[8][4];
#pragma unroll
        for (int nt = 0; nt < 8; nt++)
#pragma unroll
            for (int r = 0; r < 4; r++) s[nt][r] = 0.f;
#pragma unroll
        for (int kt = 0; kt < 4; kt++) {
#pragma unroll
            for (int hf = 0; hf < 2; hf++) {
                uint32_t b_h[2][4], b_l[2][4];
#pragma unroll
                for (int j = 0; j < 2; j++) {
                    const int nt2 = hf * 2 + j;
                    const uint32_t rb = st +
                        (uint32_t)(nt2 * 16 + (lane >> 4) * 8 + (lane & 7)) * FSTR +
                        kt * 32 + ((lane >> 3) & 1) * 16;
                    ldsm4(b_h[j], rb);
                    ldsm4(b_l[j], rb + KL_O);
                }
#pragma unroll
                for (int j = 0; j < 2; j++) {
                    mma16816(s[(hf * 2 + j) * 2],     qfh[kt], b_h[j]);
                    mma16816(s[(hf * 2 + j) * 2 + 1], qfh[kt], b_h[j] + 2);
                }
#pragma unroll
                for (int j = 0; j < 2; j++) {
                    mma16816(s[(hf * 2 + j) * 2],     qfh[kt], b_l[j]);
                    mma16816(s[(hf * 2 + j) * 2 + 1], qfh[kt], b_l[j] + 2);
                }
            }
        }

        // ---- scale + mask + online softmax ----
        float ra = -CUDART_INF_F, rbx = -CUDART_INF_F;
#pragma unroll
        for (int nt = 0; nt < 8; nt++) {
            const int kk = nt * 8 + qc * 2;
            const uint32_t wA = (nt < 4) ? wa.x : wa.y;
            const uint32_t wB = (nt < 4) ? wb.x : wb.y;
            const int bit = kk & 31;
            s[nt][0] = ((wA >> bit) & 1)       ? s[nt][0] * 0.125f : -1e9f;
            s[nt][1] = ((wA >> (bit + 1)) & 1) ? s[nt][1] * 0.125f : -1e9f;
            s[nt][2] = ((wB >> bit) & 1)       ? s[nt][2] * 0.125f : -1e9f;
            s[nt][3] = ((wB >> (bit + 1)) & 1) ? s[nt][3] * 0.125f : -1e9f;
            ra  = fmaxf(ra,  fmaxf(s[nt][0], s[nt][1]));
            rbx = fmaxf(rbx, fmaxf(s[nt][2], s[nt][3]));
        }
        ra = qmax(ra); rbx = qmax(rbx);
        const float mna = fmaxf(m_a, ra), mnb = fmaxf(m_b, rbx);
        const float ca = __expf(m_a - mna), cb = __expf(m_b - mnb);
        float suma = 0.f, sumb = 0.f;
#pragma unroll
        for (int nt = 0; nt < 8; nt++) {
            s[nt][0] = __expf(s[nt][0] - mna);
            s[nt][1] = __expf(s[nt][1] - mna);
            s[nt][2] = __expf(s[nt][2] - mnb);
            s[nt][3] = __expf(s[nt][3] - mnb);
            suma += s[nt][0] + s[nt][1];
            sumb += s[nt][2] + s[nt][3];
        }
        l_a = l_a * ca + qsum(suma);
        l_b = l_b * cb + qsum(sumb);
#pragma unroll
        for (int nt = 0; nt < 8; nt++) {
            acc_o[nt][0] *= ca; acc_o[nt][1] *= ca;
            acc_o[nt][2] *= cb; acc_o[nt][3] *= cb;
        }
        m_a = mna; m_b = mnb;

        // ---- P @ V: (Ph + Pl)·Vh (2-pass, P split in registers) ----
#pragma unroll
        for (int kt2 = 0; kt2 < 4; kt2++) {
            uint32_t p_h[4], p_l[4];
            split2(s[2 * kt2][0],     s[2 * kt2][1],     p_h[0], p_l[0]);
            split2(s[2 * kt2][2],     s[2 * kt2][3],     p_h[1], p_l[1]);
            split2(s[2 * kt2 + 1][0], s[2 * kt2 + 1][1], p_h[2], p_l[2]);
            split2(s[2 * kt2 + 1][2], s[2 * kt2 + 1][3], p_h[3], p_l[3]);
#pragma unroll
            for (int hf = 0; hf < 2; hf++) {
                uint32_t v_h[2][4];
#pragma unroll
                for (int j = 0; j < 2; j++) {
                    const int nd2 = hf * 2 + j;
                    const uint32_t vb = st + VH_O +
                        (uint32_t)(kt2 * 16 + ((lane >> 3) & 1) * 8 + (lane & 7)) * FSTR +
                        nd2 * 32 + (lane >> 4) * 16;
                    ldsm4t(v_h[j], vb);
                }
#pragma unroll
                for (int j = 0; j < 2; j++) {
                    mma16816(acc_o[(hf * 2 + j) * 2],     p_h, v_h[j]);
                    mma16816(acc_o[(hf * 2 + j) * 2 + 1], p_h, v_h[j] + 2);
                }
#pragma unroll
                for (int j = 0; j < 2; j++) {
                    mma16816(acc_o[(hf * 2 + j) * 2],     p_l, v_h[j]);
                    mma16816(acc_o[(hf * 2 + j) * 2 + 1], p_l, v_h[j] + 2);
                }
            }
        }
    }

    // epilogue: x hi-only fp16
    const float inva = 1.f / l_a, invb = 1.f / l_b;
#pragma unroll
    for (int nt = 0; nt < 8; nt++) {
        const int col = h * Dk + nt * 8 + qc * 2;
        size_t idx = ((size_t)b * Ssz + row_a) * Dm + col;
        *(uint32_t*)&xh[idx] = pack_f16(acc_o[nt][0] * inva, acc_o[nt][1] * inva);
        idx = ((size_t)b * Ssz + row_a + 8) * Dm + col;
        *(uint32_t*)&xh[idx] = pack_f16(acc_o[nt][2] * invb, acc_o[nt][3] * invb);
    }
}

// ---------------- launch ----------------------------------------------------
extern "C" void kernel_launch(void* const* d_in, const int* in_sizes, int n_in,
                              void* d_out, int out_size)
{
    (void)in_sizes; (void)n_in; (void)out_size;
    const float* query  = (const float*)d_in[0];
    const float* key_in = (const float*)d_in[1];
    const float* value  = (const float*)d_in[2];
    const int*   mask   = (const int*)  d_in[3];
    const float* Wq = (const float*)d_in[4];
    const float* bq = (const float*)d_in[5];
    const float* Wk = (const float*)d_in[6];
    const float* bk = (const float*)d_in[7];
    const float* Wv = (const float*)d_in[8];
    const float* bv = (const float*)d_in[9];
    const float* Wo = (const float*)d_in[10];
    const float* bo = (const float*)d_in[11];
    float* out = (float*)d_out;

    __half* ah;
    uint32_t* mbp;
    cudaGetSymbolAddress((void**)&ah, g_ah);
    cudaGetSymbolAddress((void**)&mbp, g_mb);

    cudaFuncSetAttribute(tgemm<0>, cudaFuncAttributeMaxDynamicSharedMemorySize, GEMM_SMEM);
    cudaFuncSetAttribute(tgemm<1>, cudaFuncAttributeMaxDynamicSharedMemorySize, GEMM_SMEM);
    cudaFuncSetAttribute(flash, cudaFuncAttributeMaxDynamicSharedMemorySize, FLASH_SMEM);

    // mask pack
    maskpack_kernel<<<(Bsz * Ssz * Ssz) / 256, 256>>>(mask, mbp);
    // fused conversions
    dim3 wgrid((Dm * Dm / 4) / 256, 1, 4);
    cvtW_kernel<<<wgrid, 256>>>(Wq, Wk, Wv, Wo);
    dim3 agrid((int)((MD / 4) / 256), 1, 3);
    cvtA_kernel<<<agrid, 256>>>(query, key_in, value);
    // fused Q/K/V projections
    dim3 pgrid(Dm / 128, 8192 / 128, 3);
    tgemm<1><<<pgrid, 256, GEMM_SMEM>>>(bq, bk, bv, nullptr);
    // attention (x hi -> activation slot 0)
    dim3 fgrid(Ssz / FQ, Hh, Bsz);
    flash<<<fgrid, 256, FLASH_SMEM>>>(mbp, ah);
    // output projection
    dim3 ogrid(Dm / 128, 8192 / 128);
    tgemm<0><<<ogrid, 256, GEMM_SMEM>>>(bo, nullptr, nullptr, out);
}

// round 9
// speedup vs baseline: 9.7130x; 1.0861x over previous
#include <cuda_runtime.h>
#include <cuda_fp16.h>
#include <math_constants.h>
#include <cstdint>

#define Bsz 4
#define Ssz 2048
#define Dm  1024
#define Hh  16
#define Dk  64
#define BH  (Bsz * Hh)
#define MD  ((size_t)8192 * 1024)
#define DD  ((size_t)1024 * 1024)

// ---------------- scratch (device globals; no allocation allowed) ----------
__device__ __align__(1024) __half g_qh[MD];            // Q hi (head-split)
__device__ __align__(1024) __half g_kh[MD];            // K hi
__device__ __align__(1024) __half g_kl[MD];            // K lo
__device__ __align__(1024) __half g_vh[MD];            // V hi
__device__ __align__(1024) __half g_ah[3 * MD];        // activations hi (q,k,v); slot0 reused for x
__device__ __align__(1024) __half g_wh[4 * DD];        // weights hi (Wq,Wk,Wv,Wo)
__device__ __align__(1024) __half g_wl[4 * DD];        // weights lo
__device__ __align__(1024) uint32_t g_mb[(size_t)Bsz * Ssz * (Ssz / 32)];

// ---------------- PTX helpers ----------------------------------------------
__device__ __forceinline__ uint32_t smem_u32(const void* p) {
    uint32_t a;
    asm("{ .reg .u64 t; cvta.to.shared.u64 t, %1; cvt.u32.u64 %0, t; }" : "=r"(a) : "l"(p));
    return a;
}
__device__ __forceinline__ void cp16(uint32_t dst, const void* src) {
    asm volatile("cp.async.cg.shared.global [%0], [%1], 16;" :: "r"(dst), "l"(src));
}
__device__ __forceinline__ void cp_commit() { asm volatile("cp.async.commit_group;"); }
__device__ __forceinline__ void cp_wait0()  { asm volatile("cp.async.wait_group 0;"); }

__device__ __forceinline__ void ldsm4(uint32_t* r, uint32_t a) {
    asm volatile("ldmatrix.sync.aligned.m8n8.x4.shared.b16 {%0,%1,%2,%3}, [%4];"
                 : "=r"(r[0]), "=r"(r[1]), "=r"(r[2]), "=r"(r[3]) : "r"(a));
}
__device__ __forceinline__ void ldsm4t(uint32_t* r, uint32_t a) {
    asm volatile("ldmatrix.sync.aligned.m8n8.x4.trans.shared.b16 {%0,%1,%2,%3}, [%4];"
                 : "=r"(r[0]), "=r"(r[1]), "=r"(r[2]), "=r"(r[3]) : "r"(a));
}
__device__ __forceinline__ void mma16816(float* d, const uint32_t* a, const uint32_t* b) {
    asm volatile("mma.sync.aligned.m16n8k16.row.col.f32.f16.f16.f32 "
                 "{%0,%1,%2,%3}, {%4,%5,%6,%7}, {%8,%9}, {%0,%1,%2,%3};"
                 : "+f"(d[0]), "+f"(d[1]), "+f"(d[2]), "+f"(d[3])
                 : "r"(a[0]), "r"(a[1]), "r"(a[2]), "r"(a[3]), "r"(b[0]), "r"(b[1]));
}
__device__ __forceinline__ uint32_t pack_f16(float lo, float hi) {
    uint32_t r;
    asm("cvt.rn.f16x2.f32 %0, %1, %2;" : "=r"(r) : "f"(hi), "f"(lo));
    return r;
}
__device__ __forceinline__ void split2(float v0, float v1, uint32_t& hp, uint32_t& lp) {
    hp = pack_f16(v0, v1);
    __half2 h2 = *reinterpret_cast<__half2*>(&hp);
    float r0 = v0 - __half2float(h2.x);
    float r1 = v1 - __half2float(h2.y);
    lp = pack_f16(r0, r1);
}
__device__ __forceinline__ float qmax(float v) {
    v = fmaxf(v, __shfl_xor_sync(0xffffffffu, v, 1));
    v = fmaxf(v, __shfl_xor_sync(0xffffffffu, v, 2));
    return v;
}
__device__ __forceinline__ float qsum(float v) {
    v += __shfl_xor_sync(0xffffffffu, v, 1);
    v += __shfl_xor_sync(0xffffffffu, v, 2);
    return v;
}

// ---------------- fused fp32 -> fp16 conversions ----------------------------
__global__ __launch_bounds__(256)
void cvtW_kernel(const float* __restrict__ w0, const float* __restrict__ w1,
                 const float* __restrict__ w2, const float* __restrict__ w3)
{
    const int z = blockIdx.z;
    const float* src = (z == 0) ? w0 : (z == 1) ? w1 : (z == 2) ? w2 : w3;
    __half* hi = g_wh + (size_t)z * DD;
    __half* lo = g_wl + (size_t)z * DD;
    const int i = blockIdx.x * 256 + threadIdx.x;
    float4 v = ((const float4*)src)[i];
    uint32_t h0, l0, h1, l1;
    split2(v.x, v.y, h0, l0);
    split2(v.z, v.w, h1, l1);
    ((uint2*)hi)[i] = make_uint2(h0, h1);
    ((uint2*)lo)[i] = make_uint2(l0, l1);
}

__global__ __launch_bounds__(256)
void cvtA_kernel(const float* __restrict__ a0, const float* __restrict__ a1,
                 const float* __restrict__ a2)
{
    const int z = blockIdx.z;
    const float* src = (z == 0) ? a0 : (z == 1) ? a1 : a2;
    __half* hi = g_ah + (size_t)z * MD;
    const int i = blockIdx.x * 256 + threadIdx.x;
    float4 v = ((const float4*)src)[i];
    ((uint2*)hi)[i] = make_uint2(pack_f16(v.x, v.y), pack_f16(v.z, v.w));
}

// ---------------- mask -> bitmask pack --------------------------------------
__global__ __launch_bounds__(256)
void maskpack_kernel(const int* __restrict__ mask, uint32_t* __restrict__ bits)
{
    const int i = blockIdx.x * 256 + threadIdx.x;
    const uint32_t b = __ballot_sync(0xffffffffu, mask[i] != 0);
    if ((threadIdx.x & 31) == 0) bits[i >> 5] = b;
}

// ---------------- tensor-core 2-pass fp16 GEMM ------------------------------
#define GSTRIDE 80
#define GARR    10240
#define GSTAGE  30720            // 3 arrays (Ah, Wh, Wl)
#define GEMM_SMEM (2 * GSTAGE)

__device__ __forceinline__ void gemm_load(uint32_t sb, int stage, int c, int tid,
                                          int m0, int n0,
                                          const __half* Ah, const __half* Wh, const __half* Wl)
{
#pragma unroll
    for (int it = 0; it < 6; it++) {
        const int flat = it * 256 + tid;                 // 0..1535
        const int arr = flat / 512, rem = flat & 511;
        const int row = rem >> 2, seg = rem & 3;
        const __half* src = (arr == 0) ? Ah : (arr == 1) ? Wh : Wl;
        const int gbase = (arr == 0) ? m0 : n0;
        cp16(sb + stage * GSTAGE + arr * GARR + row * GSTRIDE + seg * 16,
             src + (size_t)(gbase + row) * Dm + c * 32 + seg * 8);
    }
    cp_commit();
}

// MODE 0: output projection -> fp32 C.  MODE 1: per-z projection -> head-split fp16.
template <int MODE>
__global__ __launch_bounds__(256, 2)
void tgemm(const float* __restrict__ b0p, const float* __restrict__ b1p,
           const float* __restrict__ b2p, float* __restrict__ C)
{
    extern __shared__ char smem[];
    const uint32_t sb = smem_u32(smem);
    const int tid = threadIdx.x;
    const int lane = tid & 31, w = tid >> 5;
    const int wm = w >> 1, wn = w & 1;
    const int m0 = blockIdx.y * 128, n0 = blockIdx.x * 128;
    const int z = (MODE == 1) ? blockIdx.z : 3;

    const __half* Ah = g_ah + ((MODE == 1) ? (size_t)z * MD : 0);
    const __half* Wh = g_wh + (size_t)z * DD;
    const __half* Wl = g_wl + (size_t)z * DD;
    const float* bias = (MODE == 0) ? b0p : (z == 0) ? b0p : (z == 1) ? b1p : b2p;
    __half* Oh = (MODE == 1) ? ((z == 0) ? g_qh : (z == 1) ? g_kh : g_vh) : nullptr;

    float acc[2][8][4];
#pragma unroll
    for (int mt = 0; mt < 2; mt++)
#pragma unroll
        for (int nt = 0; nt < 8; nt++)
#pragma unroll
            for (int r = 0; r < 4; r++) acc[mt][nt][r] = 0.f;

    gemm_load(sb, 0, 0, tid, m0, n0, Ah, Wh, Wl);

    for (int c = 0; c < 32; c++) {
        cp_wait0();
        __syncthreads();
        if (c + 1 < 32) gemm_load(sb, (c + 1) & 1, c + 1, tid, m0, n0, Ah, Wh, Wl);
        const uint32_t st = sb + (c & 1) * GSTAGE;
#pragma unroll
        for (int kt = 0; kt < 2; kt++) {
            uint32_t a_h[2][4];
#pragma unroll
            for (int mt = 0; mt < 2; mt++) {
                const uint32_t ra = st +
                    (uint32_t)(wm * 32 + mt * 16 + ((lane >> 3) & 1) * 8 + (lane & 7)) * GSTRIDE +
                    kt * 32 + (lane >> 4) * 16;
                ldsm4(a_h[mt], ra);
            }
#pragma unroll
            for (int hf = 0; hf < 2; hf++) {
                uint32_t b_h[2][4], b_l[2][4];
#pragma unroll
                for (int j = 0; j < 2; j++) {
                    const int nt2 = hf * 2 + j;
                    const uint32_t rb = st + GARR +
                        (uint32_t)(wn * 64 + nt2 * 16 + (lane >> 4) * 8 + (lane & 7)) * GSTRIDE +
                        kt * 32 + ((lane >> 3) & 1) * 16;
                    ldsm4(b_h[j], rb);
                    ldsm4(b_l[j], rb + GARR);
                }
#pragma unroll
                for (int mt = 0; mt < 2; mt++)
#pragma unroll
                    for (int j = 0; j < 2; j++) {
                        mma16816(acc[mt][(hf * 2 + j) * 2],     a_h[mt], b_h[j]);
                        mma16816(acc[mt][(hf * 2 + j) * 2 + 1], a_h[mt], b_h[j] + 2);
                    }
#pragma unroll
                for (int mt = 0; mt < 2; mt++)
#pragma unroll
                    for (int j = 0; j < 2; j++) {
                        mma16816(acc[mt][(hf * 2 + j) * 2],     a_h[mt], b_l[j]);
                        mma16816(acc[mt][(hf * 2 + j) * 2 + 1], a_h[mt], b_l[j] + 2);
                    }
            }
        }
    }

    const int grp = lane >> 2, qc = lane & 3;
#pragma unroll
    for (int mt = 0; mt < 2; mt++) {
#pragma unroll
        for (int nt = 0; nt < 8; nt++) {
            const int row = m0 + wm * 32 + mt * 16 + grp;
            const int col = n0 + wn * 64 + nt * 8 + qc * 2;
            const float b0 = bias[col], b1 = bias[col + 1];
            const float v0 = acc[mt][nt][0] + b0, v1 = acc[mt][nt][1] + b1;
            const float v2 = acc[mt][nt][2] + b0, v3 = acc[mt][nt][3] + b1;
            if (MODE == 0) {
                *(float2*)&C[(size_t)row * Dm + col]       = make_float2(v0, v1);
                *(float2*)&C[(size_t)(row + 8) * Dm + col] = make_float2(v2, v3);
            } else {
                const int hh = col >> 6, dk = col & 63;
#pragma unroll
                for (int half_i = 0; half_i < 2; half_i++) {
                    const int r2 = row + half_i * 8;
                    const int bb = r2 >> 11, s = r2 & 2047;
                    const size_t idx = (((size_t)(bb * Hh + hh)) * Ssz + s) * Dk + dk;
                    const float x0 = half_i ? v2 : v0, x1 = half_i ? v3 : v1;
                    if (z == 1) {          // K keeps hi+lo (QK 2-pass uses K-lo)
                        uint32_t hp, lp; split2(x0, x1, hp, lp);
                        *(uint32_t*)&Oh[idx] = hp;
                        *(uint32_t*)&g_kl[idx] = lp;
                    } else {               // Q, V: hi only
                        *(uint32_t*)&Oh[idx] = pack_f16(x0, x1);
                    }
                }
            }
        }
    }
}

// ---------------- flash attention: fp16, 2-pass QK, 1-pass PV ---------------
#define FQ 128
#define FK 64
#define FSTR 144
#define QH_OFF 0
#define KV_OFF 18432
#define KVST   27648            // per stage: kh, kl, vh (9216 each)
#define KL_O 9216
#define VH_O 18432
#define FLASH_SMEM 73728        // 72 KB -> 2 CTAs/SM

__device__ __forceinline__ void flash_load_kv(uint32_t sb, int j, int tid, size_t bh)
{
#pragma unroll
    for (int it = 0; it < 6; it++) {
        const int flat = it * 256 + tid;                 // 0..1535
        const int arr = flat / 512, rem = flat & 511;
        const int row = rem >> 3, seg = rem & 7;
        const __half* src = (arr == 0) ? g_kh : (arr == 1) ? g_kl : g_vh;
        cp16(sb + KV_OFF + (j & 1) * KVST + arr * 9216 + row * FSTR + seg * 16,
             src + (bh * Ssz + j * FK + row) * Dk + seg * 8);
    }
    cp_commit();
}

__global__ __launch_bounds__(256, 2)
void flash(const uint32_t* __restrict__ mb, __half* __restrict__ xh)
{
    extern __shared__ char smem[];
    const uint32_t sb = smem_u32(smem);
    const int tid = threadIdx.x, lane = tid & 31, w = tid >> 5;
    const int b = blockIdx.z, h = blockIdx.y, q0 = blockIdx.x * FQ;
    const size_t bh = (size_t)(b * Hh + h);
    const int grp = lane >> 2, qc = lane & 3;
    const int row_a = q0 + w * 16 + grp;

    flash_load_kv(sb, 0, tid, bh);
#pragma unroll
    for (int it = 0; it < 4; it++) {
        const int flat = it * 256 + tid;                 // 0..1023
        const int row = flat >> 3, seg = flat & 7;
        cp16(sb + QH_OFF + row * FSTR + seg * 16,
             g_qh + (bh * Ssz + q0 + row) * Dk + seg * 8);
    }
    cp_commit();
    cp_wait0();
    __syncthreads();

    // hoist loop-invariant Q-hi fragments
    const uint32_t qrow = (uint32_t)(w * 16 + ((lane >> 3) & 1) * 8 + (lane & 7)) * FSTR +
                          (lane >> 4) * 16;
    uint32_t qfh[4][4];
#pragma unroll
    for (int kt = 0; kt < 4; kt++) ldsm4(qfh[kt], sb + QH_OFF + qrow + kt * 32);

    float acc_o[8][4];
#pragma unroll
    for (int nt = 0; nt < 8; nt++)
#pragma unroll
        for (int r = 0; r < 4; r++) acc_o[nt][r] = 0.f;
    float m_a = -CUDART_INF_F, m_b = -CUDART_INF_F, l_a = 0.f, l_b = 0.f;

    const uint32_t* mrow_a = mb + ((size_t)b * Ssz + row_a) * (Ssz / 32);
    const uint32_t* mrow_b = mrow_a + 8 * (Ssz / 32);

    const int NJT = Ssz / FK;   // 32
    for (int jt = 0; jt < NJT; jt++) {
        const uint2 wa = *(const uint2*)(mrow_a + jt * 2);
        const uint2 wb = *(const uint2*)(mrow_b + jt * 2);
        if (jt > 0) { cp_wait0(); __syncthreads(); }
        if (jt + 1 < NJT) flash_load_kv(sb, jt + 1, tid, bh);
        const uint32_t st = sb + KV_OFF + (jt & 1) * KVST;

        // ---- QK^T: Qh·Kh + Qh·Kl (2-pass) ----
        float s[8][4];
#pragma unroll
        for (int nt = 0; nt < 8; nt++)
#pragma unroll
            for (int r = 0; r < 4; r++) s[nt][r] = 0.f;
#pragma unroll
        for (int kt = 0; kt < 4; kt++) {
#pragma unroll
            for (int hf = 0; hf < 2; hf++) {
                uint32_t b_h[2][4], b_l[2][4];
#pragma unroll
                for (int j = 0; j < 2; j++) {
                    const int nt2 = hf * 2 + j;
                    const uint32_t rb = st +
                        (uint32_t)(nt2 * 16 + (lane >> 4) * 8 + (lane & 7)) * FSTR +
                        kt * 32 + ((lane >> 3) & 1) * 16;
                    ldsm4(b_h[j], rb);
                    ldsm4(b_l[j], rb + KL_O);
                }
#pragma unroll
                for (int j = 0; j < 2; j++) {
                    mma16816(s[(hf * 2 + j) * 2],     qfh[kt], b_h[j]);
                    mma16816(s[(hf * 2 + j) * 2 + 1], qfh[kt], b_h[j] + 2);
                }
#pragma unroll
                for (int j = 0; j < 2; j++) {
                    mma16816(s[(hf * 2 + j) * 2],     qfh[kt], b_l[j]);
                    mma16816(s[(hf * 2 + j) * 2 + 1], qfh[kt], b_l[j] + 2);
                }
            }
        }

        // ---- scale + mask + online softmax (fp32 exp, fp32 sums) ----
        float ra = -CUDART_INF_F, rbx = -CUDART_INF_F;
#pragma unroll
        for (int nt = 0; nt < 8; nt++) {
            const int kk = nt * 8 + qc * 2;
            const uint32_t wA = (nt < 4) ? wa.x : wa.y;
            const uint32_t wB = (nt < 4) ? wb.x : wb.y;
            const int bit = kk & 31;
            s[nt][0] = ((wA >> bit) & 1)       ? s[nt][0] * 0.125f : -1e9f;
            s[nt][1] = ((wA >> (bit + 1)) & 1) ? s[nt][1] * 0.125f : -1e9f;
            s[nt][2] = ((wB >> bit) & 1)       ? s[nt][2] * 0.125f : -1e9f;
            s[nt][3] = ((wB >> (bit + 1)) & 1) ? s[nt][3] * 0.125f : -1e9f;
            ra  = fmaxf(ra,  fmaxf(s[nt][0], s[nt][1]));
            rbx = fmaxf(rbx, fmaxf(s[nt][2], s[nt][3]));
        }
        ra = qmax(ra); rbx = qmax(rbx);
        const float mna = fmaxf(m_a, ra), mnb = fmaxf(m_b, rbx);
        const float ca = __expf(m_a - mna), cb = __expf(m_b - mnb);
        float suma = 0.f, sumb = 0.f;
#pragma unroll
        for (int nt = 0; nt < 8; nt++) {
            s[nt][0] = __expf(s[nt][0] - mna);
            s[nt][1] = __expf(s[nt][1] - mna);
            s[nt][2] = __expf(s[nt][2] - mnb);
            s[nt][3] = __expf(s[nt][3] - mnb);
            suma += s[nt][0] + s[nt][1];
            sumb += s[nt][2] + s[nt][3];
        }
        l_a = l_a * ca + qsum(suma);
        l_b = l_b * cb + qsum(sumb);
#pragma unroll
        for (int nt = 0; nt < 8; nt++) {
            acc_o[nt][0] *= ca; acc_o[nt][1] *= ca;
            acc_o[nt][2] *= cb; acc_o[nt][3] *= cb;
        }
        m_a = mna; m_b = mnb;

        // ---- P @ V: single pass, P rounded to fp16 in registers ----
#pragma unroll
        for (int kt2 = 0; kt2 < 4; kt2++) {
            uint32_t p_h[4];
            p_h[0] = pack_f16(s[2 * kt2][0],     s[2 * kt2][1]);
            p_h[1] = pack_f16(s[2 * kt2][2],     s[2 * kt2][3]);
            p_h[2] = pack_f16(s[2 * kt2 + 1][0], s[2 * kt2 + 1][1]);
            p_h[3] = pack_f16(s[2 * kt2 + 1][2], s[2 * kt2 + 1][3]);
#pragma unroll
            for (int hf = 0; hf < 2; hf++) {
                uint32_t v_h[2][4];
#pragma unroll
                for (int j = 0; j < 2; j++) {
                    const int nd2 = hf * 2 + j;
                    const uint32_t vb = st + VH_O +
                        (uint32_t)(kt2 * 16 + ((lane >> 3) & 1) * 8 + (lane & 7)) * FSTR +
                        nd2 * 32 + (lane >> 4) * 16;
                    ldsm4t(v_h[j], vb);
                }
#pragma unroll
                for (int j = 0; j < 2; j++) {
                    mma16816(acc_o[(hf * 2 + j) * 2],     p_h, v_h[j]);
                    mma16816(acc_o[(hf * 2 + j) * 2 + 1], p_h, v_h[j] + 2);
                }
            }
        }
    }

    // epilogue: x hi-only fp16
    const float inva = 1.f / l_a, invb = 1.f / l_b;
#pragma unroll
    for (int nt = 0; nt < 8; nt++) {
        const int col = h * Dk + nt * 8 + qc * 2;
        size_t idx = ((size_t)b * Ssz + row_a) * Dm + col;
        *(uint32_t*)&xh[idx] = pack_f16(acc_o[nt][0] * inva, acc_o[nt][1] * inva);
        idx = ((size_t)b * Ssz + row_a + 8) * Dm + col;
        *(uint32_t*)&xh[idx] = pack_f16(acc_o[nt][2] * invb, acc_o[nt][3] * invb);
    }
}

// ---------------- launch ----------------------------------------------------
extern "C" void kernel_launch(void* const* d_in, const int* in_sizes, int n_in,
                              void* d_out, int out_size)
{
    (void)in_sizes; (void)n_in; (void)out_size;
    const float* query  = (const float*)d_in[0];
    const float* key_in = (const float*)d_in[1];
    const float* value  = (const float*)d_in[2];
    const int*   mask   = (const int*)  d_in[3];
    const float* Wq = (const float*)d_in[4];
    const float* bq = (const float*)d_in[5];
    const float* Wk = (const float*)d_in[6];
    const float* bk = (const float*)d_in[7];
    const float* Wv = (const float*)d_in[8];
    const float* bv = (const float*)d_in[9];
    const float* Wo = (const float*)d_in[10];
    const float* bo = (const float*)d_in[11];
    float* out = (float*)d_out;

    __half* ah;
    uint32_t* mbp;
    cudaGetSymbolAddress((void**)&ah, g_ah);
    cudaGetSymbolAddress((void**)&mbp, g_mb);

    cudaFuncSetAttribute(tgemm<0>, cudaFuncAttributeMaxDynamicSharedMemorySize, GEMM_SMEM);
    cudaFuncSetAttribute(tgemm<1>, cudaFuncAttributeMaxDynamicSharedMemorySize, GEMM_SMEM);
    cudaFuncSetAttribute(flash, cudaFuncAttributeMaxDynamicSharedMemorySize, FLASH_SMEM);

    // mask pack
    maskpack_kernel<<<(Bsz * Ssz * Ssz) / 256, 256>>>(mask, mbp);
    // fused conversions
    dim3 wgrid((Dm * Dm / 4) / 256, 1, 4);
    cvtW_kernel<<<wgrid, 256>>>(Wq, Wk, Wv, Wo);
    dim3 agrid((int)((MD / 4) / 256), 1, 3);
    cvtA_kernel<<<agrid, 256>>>(query, key_in, value);
    // fused Q/K/V projections
    dim3 pgrid(Dm / 128, 8192 / 128, 3);
    tgemm<1><<<pgrid, 256, GEMM_SMEM>>>(bq, bk, bv, nullptr);
    // attention (x hi -> activation slot 0)
    dim3 fgrid(Ssz / FQ, Hh, Bsz);
    flash<<<fgrid, 256, FLASH_SMEM>>>(mbp, ah);
    // output projection
    dim3 ogrid(Dm / 128, 8192 / 128);
    tgemm<0><<<ogrid, 256, GEMM_SMEM>>>(bo, nullptr, nullptr, out);
}